// round 9
// baseline (speedup 1.0000x reference)
#include <cuda_runtime.h>
#include <cuda_bf16.h>
#include <cstdint>
#include <math.h>

// ---------------------------------------------------------------------------
// BackbonePointNet on GB300, round 9. HMMA bf16 hi/lo split (rel_err=0.0 in
// R7/R8). R8 post-mortem: tiles were phase-serialized through an X smem
// staging buffer that also capped occupancy. Fix: gather A DIRECTLY into MMA
// fragments (per-lane 8B LDGs at fragment coordinates), relu+split in regs.
// No X smem, fewer barriers, 128-edge tiles (1 node per warp), higher
// occupancy. W stays in smem (prefetch-double-buffered fragments).
// ---------------------------------------------------------------------------

#define MAXN 100000
__device__ float g_A[MAXN * 128];
__device__ float g_h1[MAXN * 64];
__device__ float g_h2[MAXN * 64];
__device__ float g_h3[MAXN * 128];
__device__ float g_part[64 * 8 * 128];
__device__ float g_pool[64 * 128];

// --------------------------- small asm helpers ------------------------------
__device__ __forceinline__ void mma16816(float* c, const uint32_t* a,
                                         uint32_t b0, uint32_t b1) {
    asm volatile(
        "mma.sync.aligned.m16n8k16.row.col.f32.bf16.bf16.f32 "
        "{%0,%1,%2,%3}, {%4,%5,%6,%7}, {%8,%9}, {%0,%1,%2,%3};"
        : "+f"(c[0]), "+f"(c[1]), "+f"(c[2]), "+f"(c[3])
        : "r"(a[0]), "r"(a[1]), "r"(a[2]), "r"(a[3]), "r"(b0), "r"(b1));
}

// relu(a-p) for a pair, then bf16 hi (packed) and lo (packed) splits.
__device__ __forceinline__ void cvt_pair(float a0, float a1, float p0, float p1,
                                         uint32_t& h, uint32_t& l) {
    float x0 = fmaxf(a0 - p0, 0.f), x1 = fmaxf(a1 - p1, 0.f);
    asm("cvt.rn.bf16x2.f32 %0, %1, %2;" : "=r"(h) : "f"(x1), "f"(x0));
    float f0 = __uint_as_float(h << 16);
    float f1 = __uint_as_float(h & 0xffff0000u);
    asm("cvt.rn.bf16x2.f32 %0, %1, %2;" : "=r"(l) : "f"(x1 - f1), "f"(x0 - f0));
}

__device__ __forceinline__ unsigned long long pk2(float lo, float hi) {
    unsigned long long d;
    asm("mov.b64 %0, {%1, %2};" : "=l"(d)
        : "r"(__float_as_uint(lo)), "r"(__float_as_uint(hi)));
    return d;
}
__device__ __forceinline__ void upk2(unsigned long long v, float& lo, float& hi) {
    unsigned int a, b;
    asm("mov.b64 {%0, %1}, %2;" : "=r"(a), "=r"(b) : "l"(v));
    lo = __uint_as_float(a);
    hi = __uint_as_float(b);
}
__device__ __forceinline__ unsigned long long ffma2(unsigned long long a,
                                                    unsigned long long b,
                                                    unsigned long long c) {
    unsigned long long d;
    asm("fma.rn.f32x2 %0, %1, %2, %3;" : "=l"(d) : "l"(a), "l"(b), "l"(c));
    return d;
}

// ---------------------------------------------------------------------------
// Per-node GEMM1 (fp32 SIMT): A[n] = hin[n]@Wa[0:HC] + pos[n]@Wa_p + ba
// ---------------------------------------------------------------------------
template <int HC, int H>
__global__ __launch_bounds__(256)
void node_kernel(const float* __restrict__ hin, const float* __restrict__ pos,
                 const float* __restrict__ Wa, const float* __restrict__ ba,
                 float* __restrict__ A, int N) {
    constexpr int CIN  = HC + 3;
    constexpr int CINP = (CIN + 3) & ~3;
    extern __shared__ float sm[];
    float* Xs = sm;
    float* Ws = Xs + 128 * CINP;
    const int tid = threadIdx.x;
    const int n0  = blockIdx.x * 128;

    for (int idx = tid; idx < CINP * H; idx += 256) {
        int k = idx / H, c = idx - k * H;
        Ws[idx] = (k < CIN) ? Wa[k * H + c] : 0.f;
    }
    for (int idx = tid; idx < 128 * CINP; idx += 256) {
        int r = idx / CINP, k = idx - r * CINP;
        int n = n0 + r;
        float v = 0.f;
        if (n < N) {
            if (k < HC) v = hin[n * HC + k];
            else if (k < CIN) v = pos[n * 3 + (k - HC)];
        }
        Xs[idx] = v;
    }
    __syncthreads();

    const int tx = tid & 15, ty = tid >> 4;
    for (int cb = 0; cb < H; cb += 64) {
        unsigned long long acc[8][2];
#pragma unroll
        for (int j = 0; j < 2; ++j) {
            unsigned long long bv =
                *(const unsigned long long*)(ba + cb + 2 * (tx + 16 * j));
#pragma unroll
            for (int i = 0; i < 8; ++i) acc[i][j] = bv;
        }
#pragma unroll 4
        for (int k = 0; k < CINP; ++k) {
            unsigned long long w0 =
                *(const unsigned long long*)(Ws + k * H + cb + 2 * tx);
            unsigned long long w1 =
                *(const unsigned long long*)(Ws + k * H + cb + 2 * (tx + 16));
#pragma unroll
            for (int i = 0; i < 8; ++i) {
                float x = Xs[(ty + 16 * i) * CINP + k];
                unsigned long long xp = pk2(x, x);
                acc[i][0] = ffma2(xp, w0, acc[i][0]);
                acc[i][1] = ffma2(xp, w1, acc[i][1]);
            }
        }
#pragma unroll
        for (int i = 0; i < 8; ++i) {
            int n = n0 + ty + 16 * i;
            if (n < N) {
#pragma unroll
                for (int j = 0; j < 2; ++j) {
                    float lo, hi;
                    upk2(acc[i][j], lo, hi);
                    *(float2*)(A + n * H + cb + 2 * (tx + 16 * j)) =
                        make_float2(lo, hi);
                }
            }
        }
    }
}

// ---------------------------------------------------------------------------
// Edge kernel via HMMA, direct-gather fragments. One CTA tile = 128 edges =
// 8 nodes; warp w owns node w (16 rows = one m16 tile). No X staging.
// MAXB: CTAs/SM via launch bounds (3 for layers 1-2, 2 for layer 3).
// ---------------------------------------------------------------------------
template <int H, int COUT, int MAXB>
__global__ __launch_bounds__(256, MAXB)
void edge_mma_kernel(const float* __restrict__ A, const float* __restrict__ pos,
                     const int* __restrict__ src, const float* __restrict__ Wap,
                     const float* __restrict__ Wb, const float* __restrict__ bb,
                     float* __restrict__ hout, int N, int E, int tiles) {
    constexpr int TPB = 256;
    constexpr int SX  = H + 8;      // bf16 elems per padded W row
    constexpr int KC  = H / 16;     // k16 chunks
    constexpr int NB  = COUT / 8;   // n8 blocks
    constexpr int NCH = 2;          // accumulator chains (kc parity)

    extern __shared__ char smem[];
    __nv_bfloat16* Wh = (__nv_bfloat16*)smem;        // [COUT][SX]
    __nv_bfloat16* Wl = Wh + COUT * SX;
    float* Pd  = (float*)(Wl + COUT * SX);           // [8][H]
    int* ssrc  = (int*)(Pd + 8 * H);                 // [128]

    const int tid = threadIdx.x, wid = tid >> 5, lane = tid & 31;
    const int r = lane >> 2, q = lane & 3;

    // Stage weights once. Wb gmem layout: [H][COUT] -> smem [COUT][SX] hi/lo.
    for (int idx = tid; idx < H * COUT; idx += TPB) {
        int k = idx / COUT, n = idx - k * COUT;
        float w = Wb[idx];
        __nv_bfloat16 hb = __float2bfloat16(w);
        __nv_bfloat16 lb = __float2bfloat16(w - __bfloat162float(hb));
        Wh[n * SX + k] = hb;
        Wl[n * SX + k] = lb;
    }

    for (int t = blockIdx.x; t < tiles; t += gridDim.x) {
        const int n0 = t * 8;           // 8 nodes per tile
        const int e0 = t * 128;
        __syncthreads();  // prior-tile readers of Pd/ssrc done (orders W too)

        if (tid < 128) ssrc[tid] = (e0 + tid < E) ? src[e0 + tid] : 0;
        for (int idx = tid; idx < 8 * H; idx += TPB) {
            int g = idx / H, c = idx - g * H;
            int n = min(n0 + g, N - 1);
            Pd[idx] = pos[n * 3] * __ldg(&Wap[c]) +
                      pos[n * 3 + 1] * __ldg(&Wap[H + c]) +
                      pos[n * 3 + 2] * __ldg(&Wap[2 * H + c]);
        }
        __syncthreads();

        // --- direct-gather A fragments: rows 16*wid + {r, r+8}. ---
        const int s0 = ssrc[16 * wid + r];
        const int s1 = ssrc[16 * wid + r + 8];
        const float* a0p = A + (size_t)s0 * H;
        const float* a1p = A + (size_t)s1 * H;
        const float* prow = Pd + wid * H;

        uint32_t ah[KC][4], al[KC][4];
#pragma unroll
        for (int kc = 0; kc < KC; ++kc) {
            const int cA = kc * 16 + 2 * q;      // pr>>1 == 0 cols
            const int cB = cA + 8;               // pr>>1 == 1 cols
            float2 pA = *(const float2*)(prow + cA);
            float2 pB = *(const float2*)(prow + cB);
            float2 a;
            a = *(const float2*)(a0p + cA);
            cvt_pair(a.x, a.y, pA.x, pA.y, ah[kc][0], al[kc][0]);
            a = *(const float2*)(a1p + cA);
            cvt_pair(a.x, a.y, pA.x, pA.y, ah[kc][1], al[kc][1]);
            a = *(const float2*)(a0p + cB);
            cvt_pair(a.x, a.y, pB.x, pB.y, ah[kc][2], al[kc][2]);
            a = *(const float2*)(a1p + cB);
            cvt_pair(a.x, a.y, pB.x, pB.y, ah[kc][3], al[kc][3]);
        }

        // --- N loop: prefetched B frags, 3-term split MMA, fragment max. ---
        uint32_t bf[2][4];
        {
            size_t o0 = ((size_t)r * SX + 2 * q) * 2;
            bf[0][0] = *(const uint32_t*)((const char*)Wh + o0);
            bf[0][1] = *(const uint32_t*)((const char*)Wh + o0 + 16);
            bf[0][2] = *(const uint32_t*)((const char*)Wl + o0);
            bf[0][3] = *(const uint32_t*)((const char*)Wl + o0 + 16);
        }
        const int node = n0 + wid;
#pragma unroll
        for (int nb = 0; nb < NB; ++nb) {
            float acc[NCH][4];
#pragma unroll
            for (int ch = 0; ch < NCH; ++ch)
#pragma unroll
                for (int i = 0; i < 4; ++i) acc[ch][i] = 0.f;
#pragma unroll
            for (int kc = 0; kc < KC; ++kc) {
                const int cur = (nb * KC + kc) & 1;
                {
                    int nnb = nb, nkc = kc + 1;
                    if (nkc == KC) { nkc = 0; nnb = (nb + 1 < NB) ? nb + 1 : nb; }
                    int wn = 8 * nnb + r;
                    size_t o0 = ((size_t)wn * SX + nkc * 16 + 2 * q) * 2;
                    bf[cur ^ 1][0] = *(const uint32_t*)((const char*)Wh + o0);
                    bf[cur ^ 1][1] = *(const uint32_t*)((const char*)Wh + o0 + 16);
                    bf[cur ^ 1][2] = *(const uint32_t*)((const char*)Wl + o0);
                    bf[cur ^ 1][3] = *(const uint32_t*)((const char*)Wl + o0 + 16);
                }
                const uint32_t* b = bf[cur];
                float* a = acc[kc & (NCH - 1)];
                mma16816(a, ah[kc], b[0], b[1]);
                mma16816(a, ah[kc], b[2], b[3]);
                mma16816(a, al[kc], b[0], b[1]);
            }
            float sm0 = acc[0][0] + acc[1][0], sm1 = acc[0][1] + acc[1][1];
            float sm2 = acc[0][2] + acc[1][2], sm3 = acc[0][3] + acc[1][3];
            float m0 = fmaxf(sm0, sm2);
            float m1 = fmaxf(sm1, sm3);
            m0 = fmaxf(m0, __shfl_xor_sync(0xffffffffu, m0, 4));
            m1 = fmaxf(m1, __shfl_xor_sync(0xffffffffu, m1, 4));
            m0 = fmaxf(m0, __shfl_xor_sync(0xffffffffu, m0, 8));
            m1 = fmaxf(m1, __shfl_xor_sync(0xffffffffu, m1, 8));
            m0 = fmaxf(m0, __shfl_xor_sync(0xffffffffu, m0, 16));
            m1 = fmaxf(m1, __shfl_xor_sync(0xffffffffu, m1, 16));
            if (lane < 4 && node < N) {
                int col = 8 * nb + 2 * lane;
                float2 o;
                o.x = fmaxf(m0 + __ldg(&bb[col]), 0.f);
                o.y = fmaxf(m1 + __ldg(&bb[col + 1]), 0.f);
                *(float2*)(hout + (size_t)node * COUT + col) = o;
            }
        }
    }
}

// ---------------------------------------------------------------------------
// Deterministic two-stage mean pool (batch sorted) + regressor.
// ---------------------------------------------------------------------------
__device__ __forceinline__ int lb(const int* __restrict__ b, int n, int v) {
    int lo = 0, hi = n;
    while (lo < hi) {
        int m = (lo + hi) >> 1;
        if (b[m] < v) lo = m + 1; else hi = m;
    }
    return lo;
}

__global__ void pool1_kernel(const float* __restrict__ h3,
                             const int* __restrict__ batch, int N,
                             float* __restrict__ part) {
    int b = blockIdx.x, k = blockIdx.y, c = threadIdx.x;
    int s = lb(batch, N, b), e = lb(batch, N, b + 1);
    int len = e - s;
    int cs = s + (int)(((long long)len * k) >> 3);
    int ce = s + (int)(((long long)len * (k + 1)) >> 3);
    float s0 = 0.f, s1 = 0.f, s2 = 0.f, s3 = 0.f;
    int n = cs;
    for (; n + 3 < ce; n += 4) {
        s0 += h3[(n + 0) * 128 + c];
        s1 += h3[(n + 1) * 128 + c];
        s2 += h3[(n + 2) * 128 + c];
        s3 += h3[(n + 3) * 128 + c];
    }
    for (; n < ce; ++n) s0 += h3[n * 128 + c];
    part[(b * 8 + k) * 128 + c] = ((s0 + s1) + (s2 + s3));
}

__global__ void pool2_kernel(const float* __restrict__ part,
                             const int* __restrict__ batch, int N,
                             float* __restrict__ pool) {
    int b = blockIdx.x, c = threadIdx.x;
    int s = lb(batch, N, b), e = lb(batch, N, b + 1);
    float sum = 0.f;
#pragma unroll
    for (int k = 0; k < 8; ++k) sum += part[(b * 8 + k) * 128 + c];
    pool[b * 128 + c] = sum / fmaxf((float)(e - s), 1.f);
}

__global__ void reg_kernel(const float* __restrict__ pool,
                           const float* __restrict__ wr1, const float* __restrict__ br1,
                           const float* __restrict__ wr2, const float* __restrict__ br2,
                           float* __restrict__ out, int B) {
    int b = blockIdx.x * blockDim.x + threadIdx.x;
    if (b >= B) return;
    float o = br2[0];
    for (int j = 0; j < 64; ++j) {
        float s = br1[j];
        for (int k = 0; k < 128; ++k) s += pool[b * 128 + k] * wr1[k * 64 + j];
        o += s * wr2[j];
    }
    out[b] = 1.f / (1.f + expf(-o));
}

extern "C" void kernel_launch(void* const* d_in, const int* in_sizes, int n_in,
                              void* d_out, int out_size) {
    const float* pos   = (const float*)d_in[0];
    const int*   ei    = (const int*)d_in[1];
    const int*   batch = (const int*)d_in[2];
    const float* w1a = (const float*)d_in[4],  *b1a = (const float*)d_in[5];
    const float* w1b = (const float*)d_in[6],  *b1b = (const float*)d_in[7];
    const float* w2a = (const float*)d_in[8],  *b2a = (const float*)d_in[9];
    const float* w2b = (const float*)d_in[10], *b2b = (const float*)d_in[11];
    const float* w3a = (const float*)d_in[12], *b3a = (const float*)d_in[13];
    const float* w3b = (const float*)d_in[14], *b3b = (const float*)d_in[15];
    const float* wr1 = (const float*)d_in[16], *br1 = (const float*)d_in[17];
    const float* wr2 = (const float*)d_in[18], *br2 = (const float*)d_in[19];
    float* out = (float*)d_out;

    int N = in_sizes[0] / 3;
    int E = in_sizes[1] / 2;
    int B = out_size;
    const int* srcp = ei;

    float *Abuf, *h1, *h2, *h3, *part, *pl;
    cudaGetSymbolAddress((void**)&Abuf, g_A);
    cudaGetSymbolAddress((void**)&h1, g_h1);
    cudaGetSymbolAddress((void**)&h2, g_h2);
    cudaGetSymbolAddress((void**)&h3, g_h3);
    cudaGetSymbolAddress((void**)&part, g_part);
    cudaGetSymbolAddress((void**)&pl, g_pool);

    const int smemN1 = (128 * 8 + 8 * 64) * 4;
    const int smemN2 = (128 * 68 + 68 * 64) * 4;
    const int smemN3 = (128 * 68 + 68 * 128) * 4;
    // edge: W hi/lo + Pd + ssrc
    const int smemE12 = (2 * 64 * 72) * 2 + 8 * 64 * 4 + 512;     // ~20.9 KB
    const int smemE3  = (2 * 128 * 136) * 2 + 8 * 128 * 4 + 512;  // ~74.2 KB

    cudaFuncSetAttribute(node_kernel<3, 64>,
                         cudaFuncAttributeMaxDynamicSharedMemorySize, smemN1);
    cudaFuncSetAttribute(node_kernel<64, 64>,
                         cudaFuncAttributeMaxDynamicSharedMemorySize, smemN2);
    cudaFuncSetAttribute(node_kernel<64, 128>,
                         cudaFuncAttributeMaxDynamicSharedMemorySize, smemN3);
    cudaFuncSetAttribute(edge_mma_kernel<64, 64, 3>,
                         cudaFuncAttributeMaxDynamicSharedMemorySize, smemE12);
    cudaFuncSetAttribute(edge_mma_kernel<128, 128, 2>,
                         cudaFuncAttributeMaxDynamicSharedMemorySize, smemE3);

    int tilesN = (N + 127) / 128;
    int tilesE = (E + 127) / 128;              // 128-edge tiles
    int grid12 = tilesE < 444 ? tilesE : 444;  // 3 CTAs/SM
    int grid3  = tilesE < 296 ? tilesE : 296;  // 2 CTAs/SM

    // layer 1 (h = pos)
    node_kernel<3, 64><<<tilesN, 256, smemN1>>>(pos, pos, w1a, b1a, Abuf, N);
    edge_mma_kernel<64, 64, 3><<<grid12, 256, smemE12>>>(
        Abuf, pos, srcp, w1a + 3 * 64, w1b, b1b, h1, N, E, tilesE);
    // layer 2
    node_kernel<64, 64><<<tilesN, 256, smemN2>>>(h1, pos, w2a, b2a, Abuf, N);
    edge_mma_kernel<64, 64, 3><<<grid12, 256, smemE12>>>(
        Abuf, pos, srcp, w2a + 64 * 64, w2b, b2b, h2, N, E, tilesE);
    // layer 3
    node_kernel<64, 128><<<tilesN, 256, smemN3>>>(h2, pos, w3a, b3a, Abuf, N);
    edge_mma_kernel<128, 128, 2><<<grid3, 256, smemE3>>>(
        Abuf, pos, srcp, w3a + 64 * 128, w3b, b3b, h3, N, E, tilesE);
    // pool + regressor
    pool1_kernel<<<dim3(B, 8), 128>>>(h3, batch, N, part);
    pool2_kernel<<<B, 128>>>(part, batch, N, pl);
    reg_kernel<<<1, 64>>>(pl, wr1, br1, wr2, br2, out, B);
}

// round 10
// speedup vs baseline: 1.4715x; 1.4715x over previous
#include <cuda_runtime.h>
#include <cuda_bf16.h>
#include <cstdint>
#include <math.h>

// ---------------------------------------------------------------------------
// BackbonePointNet on GB300, round 10. HMMA bf16 hi/lo split (rel_err=0.0 in
// R7/R8). R9 (direct gather) regressed -> reverted to staged X. New: WARP
// SPECIALIZATION: producer warps gather+convert X(t+1) while consumer warps
// MMA X(t) (double-buffered), killing the phase serialization that capped
// tensor at 32%. P is per-node -> kept in producer registers (no smem/bar).
// X stored hi/lo interleaved -> consumer loads hi+lo per fragment in 1 LDS.64.
// ---------------------------------------------------------------------------

#define MAXN 100000
__device__ float g_A[MAXN * 128];
__device__ float g_h1[MAXN * 64];
__device__ float g_h2[MAXN * 64];
__device__ float g_h3[MAXN * 128];
__device__ float g_part[64 * 8 * 128];
__device__ float g_pool[64 * 128];

// --------------------------- small asm helpers ------------------------------
__device__ __forceinline__ void mma16816(float* c, const uint32_t* a,
                                         uint32_t b0, uint32_t b1) {
    asm volatile(
        "mma.sync.aligned.m16n8k16.row.col.f32.bf16.bf16.f32 "
        "{%0,%1,%2,%3}, {%4,%5,%6,%7}, {%8,%9}, {%0,%1,%2,%3};"
        : "+f"(c[0]), "+f"(c[1]), "+f"(c[2]), "+f"(c[3])
        : "r"(a[0]), "r"(a[1]), "r"(a[2]), "r"(a[3]), "r"(b0), "r"(b1));
}

// relu(a-p) for a pair, then packed bf16 hi and lo splits.
__device__ __forceinline__ void cvt_pair(float a0, float a1, float p0, float p1,
                                         uint32_t& h, uint32_t& l) {
    float x0 = fmaxf(a0 - p0, 0.f), x1 = fmaxf(a1 - p1, 0.f);
    asm("cvt.rn.bf16x2.f32 %0, %1, %2;" : "=r"(h) : "f"(x1), "f"(x0));
    float f0 = __uint_as_float(h << 16);
    float f1 = __uint_as_float(h & 0xffff0000u);
    asm("cvt.rn.bf16x2.f32 %0, %1, %2;" : "=r"(l) : "f"(x1 - f1), "f"(x0 - f0));
}

__device__ __forceinline__ unsigned long long pk2(float lo, float hi) {
    unsigned long long d;
    asm("mov.b64 %0, {%1, %2};" : "=l"(d)
        : "r"(__float_as_uint(lo)), "r"(__float_as_uint(hi)));
    return d;
}
__device__ __forceinline__ void upk2(unsigned long long v, float& lo, float& hi) {
    unsigned int a, b;
    asm("mov.b64 {%0, %1}, %2;" : "=r"(a), "=r"(b) : "l"(v));
    lo = __uint_as_float(a);
    hi = __uint_as_float(b);
}
__device__ __forceinline__ unsigned long long ffma2(unsigned long long a,
                                                    unsigned long long b,
                                                    unsigned long long c) {
    unsigned long long d;
    asm("fma.rn.f32x2 %0, %1, %2, %3;" : "=l"(d) : "l"(a), "l"(b), "l"(c));
    return d;
}

// ---------------------------------------------------------------------------
// Per-node GEMM1 (fp32 SIMT): A[n] = hin[n]@Wa[0:HC] + pos[n]@Wa_p + ba
// ---------------------------------------------------------------------------
template <int HC, int H>
__global__ __launch_bounds__(256)
void node_kernel(const float* __restrict__ hin, const float* __restrict__ pos,
                 const float* __restrict__ Wa, const float* __restrict__ ba,
                 float* __restrict__ A, int N) {
    constexpr int CIN  = HC + 3;
    constexpr int CINP = (CIN + 3) & ~3;
    extern __shared__ float sm[];
    float* Xs = sm;
    float* Ws = Xs + 128 * CINP;
    const int tid = threadIdx.x;
    const int n0  = blockIdx.x * 128;

    for (int idx = tid; idx < CINP * H; idx += 256) {
        int k = idx / H, c = idx - k * H;
        Ws[idx] = (k < CIN) ? Wa[k * H + c] : 0.f;
    }
    for (int idx = tid; idx < 128 * CINP; idx += 256) {
        int r = idx / CINP, k = idx - r * CINP;
        int n = n0 + r;
        float v = 0.f;
        if (n < N) {
            if (k < HC) v = hin[n * HC + k];
            else if (k < CIN) v = pos[n * 3 + (k - HC)];
        }
        Xs[idx] = v;
    }
    __syncthreads();

    const int tx = tid & 15, ty = tid >> 4;
    for (int cb = 0; cb < H; cb += 64) {
        unsigned long long acc[8][2];
#pragma unroll
        for (int j = 0; j < 2; ++j) {
            unsigned long long bv =
                *(const unsigned long long*)(ba + cb + 2 * (tx + 16 * j));
#pragma unroll
            for (int i = 0; i < 8; ++i) acc[i][j] = bv;
        }
#pragma unroll 4
        for (int k = 0; k < CINP; ++k) {
            unsigned long long w0 =
                *(const unsigned long long*)(Ws + k * H + cb + 2 * tx);
            unsigned long long w1 =
                *(const unsigned long long*)(Ws + k * H + cb + 2 * (tx + 16));
#pragma unroll
            for (int i = 0; i < 8; ++i) {
                float x = Xs[(ty + 16 * i) * CINP + k];
                unsigned long long xp = pk2(x, x);
                acc[i][0] = ffma2(xp, w0, acc[i][0]);
                acc[i][1] = ffma2(xp, w1, acc[i][1]);
            }
        }
#pragma unroll
        for (int i = 0; i < 8; ++i) {
            int n = n0 + ty + 16 * i;
            if (n < N) {
#pragma unroll
                for (int j = 0; j < 2; ++j) {
                    float lo, hi;
                    upk2(acc[i][j], lo, hi);
                    *(float2*)(A + n * H + cb + 2 * (tx + 16 * j)) =
                        make_float2(lo, hi);
                }
            }
        }
    }
}

// ---------------------------------------------------------------------------
// Warp-specialized edge kernel. Tile = 128 edges = 8 nodes.
// First WARPS/2 warps: producers (gather A, relu(A-P), bf16 hi/lo split, STS
// interleaved). Last WARPS/2: consumers (A-frag LDS, split MMA, seg-max).
// X double-buffered; one __syncthreads per tile.
// ---------------------------------------------------------------------------
template <int H, int COUT, int TPB, int MAXB>
__global__ __launch_bounds__(TPB, MAXB)
void edge_ws_kernel(const float* __restrict__ A, const float* __restrict__ pos,
                    const int* __restrict__ src, const float* __restrict__ Wap,
                    const float* __restrict__ Wb, const float* __restrict__ bb,
                    float* __restrict__ hout, int N, int E, int tiles) {
    constexpr int WARPS = TPB / 32;
    constexpr int PW    = WARPS / 2;    // producer warps
    constexpr int NPN   = 8 / PW;       // nodes per warp (both roles)
    constexpr int KC    = H / 16;
    constexpr int NB    = COUT / 8;
    constexpr int RS    = H * 4 + 32;   // X row bytes (hi/lo interleaved + pad)
    constexpr int SX    = H + 8;        // W padded row (bf16 elems)

    extern __shared__ char smem[];
    char* Xb[2] = {smem, smem + 128 * RS};
    __nv_bfloat16* Wh = (__nv_bfloat16*)(smem + 2 * 128 * RS);
    __nv_bfloat16* Wl = Wh + COUT * SX;

    const int tid = threadIdx.x, wid = tid >> 5, lane = tid & 31;
    const int r = lane >> 2, q = lane & 3;
    const bool isProd = wid < PW;

    // Stage W once (all threads). Wb gmem layout [H][COUT].
    for (int idx = tid; idx < H * COUT; idx += TPB) {
        int k = idx / COUT, n = idx - k * COUT;
        float w = Wb[idx];
        __nv_bfloat16 hb = __float2bfloat16(w);
        __nv_bfloat16 lb = __float2bfloat16(w - __bfloat162float(hb));
        Wh[n * SX + k] = hb;
        Wl[n * SX + k] = lb;
    }

    // ---- producer: fill Xbuf with tile t ----
    auto produce = [&](int t, char* Xbuf) {
        const int e0 = t * 128, n0t = t * 8;
        const int pw = wid;
#pragma unroll
        for (int nn = 0; nn < NPN; ++nn) {
            const int g  = pw * NPN + nn;           // node slot 0..7
            const int nd = min(n0t + g, N - 1);
            int e = e0 + 16 * g + (lane & 15);
            int srcv = (e < E) ? src[e] : 0;
            const int c4 = (H == 64) ? (lane & 15) : lane;
            float p0 = pos[nd * 3], p1 = pos[nd * 3 + 1], p2 = pos[nd * 3 + 2];
            float4 P;
            P.x = p0 * __ldg(&Wap[4 * c4 + 0]) + p1 * __ldg(&Wap[H + 4 * c4 + 0]) +
                  p2 * __ldg(&Wap[2 * H + 4 * c4 + 0]);
            P.y = p0 * __ldg(&Wap[4 * c4 + 1]) + p1 * __ldg(&Wap[H + 4 * c4 + 1]) +
                  p2 * __ldg(&Wap[2 * H + 4 * c4 + 1]);
            P.z = p0 * __ldg(&Wap[4 * c4 + 2]) + p1 * __ldg(&Wap[H + 4 * c4 + 2]) +
                  p2 * __ldg(&Wap[2 * H + 4 * c4 + 2]);
            P.w = p0 * __ldg(&Wap[4 * c4 + 3]) + p1 * __ldg(&Wap[H + 4 * c4 + 3]) +
                  p2 * __ldg(&Wap[2 * H + 4 * c4 + 3]);
            constexpr int PASSES = (H == 64) ? 8 : 16;
#pragma unroll
            for (int p = 0; p < PASSES; ++p) {
                int rowin = (H == 64) ? (2 * p + (lane >> 4)) : p;  // 0..15
                int j = __shfl_sync(0xffffffffu, srcv, rowin);
                const float4 a = ((const float4*)(A + (size_t)j * H))[c4];
                uint32_t h01, l01, h23, l23;
                cvt_pair(a.x, a.y, P.x, P.y, h01, l01);
                cvt_pair(a.z, a.w, P.z, P.w, h23, l23);
                int row = 16 * g + rowin;
                *(uint4*)(Xbuf + row * RS + c4 * 16) =
                    make_uint4(h01, l01, h23, l23);
            }
        }
    };

    // ---- consumer: MMA + seg-max for tile t ----
    auto consume = [&](int t, const char* Xbuf) {
        const int n0t = t * 8;
        const int cw  = wid - PW;

        uint32_t ah[NPN][KC][4], al[NPN][KC][4];
#pragma unroll
        for (int nn = 0; nn < NPN; ++nn) {
            const int Rb = 16 * (cw * NPN + nn);
#pragma unroll
            for (int kc = 0; kc < KC; ++kc) {
#pragma unroll
                for (int pr = 0; pr < 4; ++pr) {
                    int row  = Rb + r + 8 * (pr & 1);
                    int pair = 8 * kc + q + 4 * (pr >> 1);
                    uint2 v = *(const uint2*)(Xbuf + row * RS + pair * 8);
                    ah[nn][kc][pr] = v.x;
                    al[nn][kc][pr] = v.y;
                }
            }
        }

        uint32_t bf[2][4];
        {
            size_t o0 = ((size_t)r * SX + 2 * q) * 2;
            bf[0][0] = *(const uint32_t*)((const char*)Wh + o0);
            bf[0][1] = *(const uint32_t*)((const char*)Wh + o0 + 16);
            bf[0][2] = *(const uint32_t*)((const char*)Wl + o0);
            bf[0][3] = *(const uint32_t*)((const char*)Wl + o0 + 16);
        }
#pragma unroll
        for (int nb = 0; nb < NB; ++nb) {
            float acc[NPN][2][4];
#pragma unroll
            for (int nn = 0; nn < NPN; ++nn)
#pragma unroll
                for (int ch = 0; ch < 2; ++ch)
#pragma unroll
                    for (int i = 0; i < 4; ++i) acc[nn][ch][i] = 0.f;
#pragma unroll
            for (int kc = 0; kc < KC; ++kc) {
                const int cur = (nb * KC + kc) & 1;
                {
                    int nnb = nb, nkc = kc + 1;
                    if (nkc == KC) { nkc = 0; nnb = (nb + 1 < NB) ? nb + 1 : nb; }
                    int wn = 8 * nnb + r;
                    size_t o0 = ((size_t)wn * SX + nkc * 16 + 2 * q) * 2;
                    bf[cur ^ 1][0] = *(const uint32_t*)((const char*)Wh + o0);
                    bf[cur ^ 1][1] = *(const uint32_t*)((const char*)Wh + o0 + 16);
                    bf[cur ^ 1][2] = *(const uint32_t*)((const char*)Wl + o0);
                    bf[cur ^ 1][3] = *(const uint32_t*)((const char*)Wl + o0 + 16);
                }
                const uint32_t* b = bf[cur];
                const int ch = kc & 1;
#pragma unroll
                for (int nn = 0; nn < NPN; ++nn) {
                    mma16816(acc[nn][ch], ah[nn][kc], b[0], b[1]);
                    mma16816(acc[nn][ch], ah[nn][kc], b[2], b[3]);
                    mma16816(acc[nn][ch], al[nn][kc], b[0], b[1]);
                }
            }
#pragma unroll
            for (int nn = 0; nn < NPN; ++nn) {
                float s0 = acc[nn][0][0] + acc[nn][1][0];
                float s1 = acc[nn][0][1] + acc[nn][1][1];
                float s2 = acc[nn][0][2] + acc[nn][1][2];
                float s3 = acc[nn][0][3] + acc[nn][1][3];
                float m0 = fmaxf(s0, s2);
                float m1 = fmaxf(s1, s3);
                m0 = fmaxf(m0, __shfl_xor_sync(0xffffffffu, m0, 4));
                m1 = fmaxf(m1, __shfl_xor_sync(0xffffffffu, m1, 4));
                m0 = fmaxf(m0, __shfl_xor_sync(0xffffffffu, m0, 8));
                m1 = fmaxf(m1, __shfl_xor_sync(0xffffffffu, m1, 8));
                m0 = fmaxf(m0, __shfl_xor_sync(0xffffffffu, m0, 16));
                m1 = fmaxf(m1, __shfl_xor_sync(0xffffffffu, m1, 16));
                int node = n0t + cw * NPN + nn;
                if (lane < 4 && node < N) {
                    int col = 8 * nb + 2 * lane;
                    float2 o;
                    o.x = fmaxf(m0 + __ldg(&bb[col]), 0.f);
                    o.y = fmaxf(m1 + __ldg(&bb[col + 1]), 0.f);
                    *(float2*)(hout + (size_t)node * COUT + col) = o;
                }
            }
        }
    };

    __syncthreads();  // W staged

    const int t0 = blockIdx.x;  // grid <= tiles guaranteed by launcher
    if (isProd) produce(t0, Xb[0]);
    __syncthreads();

    for (int k = 0;; ++k) {
        int tc = t0 + k * gridDim.x;
        if (tc >= tiles) break;  // uniform across CTA
        if (isProd) {
            int tp = tc + gridDim.x;
            if (tp < tiles) produce(tp, Xb[(k + 1) & 1]);
        } else {
            consume(tc, Xb[k & 1]);
        }
        __syncthreads();
    }
}

// ---------------------------------------------------------------------------
// Deterministic two-stage mean pool (batch sorted) + regressor.
// ---------------------------------------------------------------------------
__device__ __forceinline__ int lb(const int* __restrict__ b, int n, int v) {
    int lo = 0, hi = n;
    while (lo < hi) {
        int m = (lo + hi) >> 1;
        if (b[m] < v) lo = m + 1; else hi = m;
    }
    return lo;
}

__global__ void pool1_kernel(const float* __restrict__ h3,
                             const int* __restrict__ batch, int N,
                             float* __restrict__ part) {
    int b = blockIdx.x, k = blockIdx.y, c = threadIdx.x;
    int s = lb(batch, N, b), e = lb(batch, N, b + 1);
    int len = e - s;
    int cs = s + (int)(((long long)len * k) >> 3);
    int ce = s + (int)(((long long)len * (k + 1)) >> 3);
    float s0 = 0.f, s1 = 0.f, s2 = 0.f, s3 = 0.f;
    int n = cs;
    for (; n + 3 < ce; n += 4) {
        s0 += h3[(n + 0) * 128 + c];
        s1 += h3[(n + 1) * 128 + c];
        s2 += h3[(n + 2) * 128 + c];
        s3 += h3[(n + 3) * 128 + c];
    }
    for (; n < ce; ++n) s0 += h3[n * 128 + c];
    part[(b * 8 + k) * 128 + c] = ((s0 + s1) + (s2 + s3));
}

__global__ void pool2_kernel(const float* __restrict__ part,
                             const int* __restrict__ batch, int N,
                             float* __restrict__ pool) {
    int b = blockIdx.x, c = threadIdx.x;
    int s = lb(batch, N, b), e = lb(batch, N, b + 1);
    float sum = 0.f;
#pragma unroll
    for (int k = 0; k < 8; ++k) sum += part[(b * 8 + k) * 128 + c];
    pool[b * 128 + c] = sum / fmaxf((float)(e - s), 1.f);
}

__global__ void reg_kernel(const float* __restrict__ pool,
                           const float* __restrict__ wr1, const float* __restrict__ br1,
                           const float* __restrict__ wr2, const float* __restrict__ br2,
                           float* __restrict__ out, int B) {
    int b = blockIdx.x * blockDim.x + threadIdx.x;
    if (b >= B) return;
    float o = br2[0];
    for (int j = 0; j < 64; ++j) {
        float s = br1[j];
        for (int k = 0; k < 128; ++k) s += pool[b * 128 + k] * wr1[k * 64 + j];
        o += s * wr2[j];
    }
    out[b] = 1.f / (1.f + expf(-o));
}

extern "C" void kernel_launch(void* const* d_in, const int* in_sizes, int n_in,
                              void* d_out, int out_size) {
    const float* pos   = (const float*)d_in[0];
    const int*   ei    = (const int*)d_in[1];
    const int*   batch = (const int*)d_in[2];
    const float* w1a = (const float*)d_in[4],  *b1a = (const float*)d_in[5];
    const float* w1b = (const float*)d_in[6],  *b1b = (const float*)d_in[7];
    const float* w2a = (const float*)d_in[8],  *b2a = (const float*)d_in[9];
    const float* w2b = (const float*)d_in[10], *b2b = (const float*)d_in[11];
    const float* w3a = (const float*)d_in[12], *b3a = (const float*)d_in[13];
    const float* w3b = (const float*)d_in[14], *b3b = (const float*)d_in[15];
    const float* wr1 = (const float*)d_in[16], *br1 = (const float*)d_in[17];
    const float* wr2 = (const float*)d_in[18], *br2 = (const float*)d_in[19];
    float* out = (float*)d_out;

    int N = in_sizes[0] / 3;
    int E = in_sizes[1] / 2;
    int B = out_size;
    const int* srcp = ei;

    float *Abuf, *h1, *h2, *h3, *part, *pl;
    cudaGetSymbolAddress((void**)&Abuf, g_A);
    cudaGetSymbolAddress((void**)&h1, g_h1);
    cudaGetSymbolAddress((void**)&h2, g_h2);
    cudaGetSymbolAddress((void**)&h3, g_h3);
    cudaGetSymbolAddress((void**)&part, g_part);
    cudaGetSymbolAddress((void**)&pl, g_pool);

    const int smemN1 = (128 * 8 + 8 * 64) * 4;
    const int smemN2 = (128 * 68 + 68 * 64) * 4;
    const int smemN3 = (128 * 68 + 68 * 128) * 4;
    // edge_ws: 2 X buffers (128 rows x RS bytes) + W hi/lo
    const int smemE12 = 2 * 128 * (64 * 4 + 32) + 2 * 64 * 72 * 2;    //  92160
    const int smemE3  = 2 * 128 * (128 * 4 + 32) + 2 * 128 * 136 * 2; // 208896

    cudaFuncSetAttribute(node_kernel<3, 64>,
                         cudaFuncAttributeMaxDynamicSharedMemorySize, smemN1);
    cudaFuncSetAttribute(node_kernel<64, 64>,
                         cudaFuncAttributeMaxDynamicSharedMemorySize, smemN2);
    cudaFuncSetAttribute(node_kernel<64, 128>,
                         cudaFuncAttributeMaxDynamicSharedMemorySize, smemN3);
    cudaFuncSetAttribute(edge_ws_kernel<64, 64, 256, 2>,
                         cudaFuncAttributeMaxDynamicSharedMemorySize, smemE12);
    cudaFuncSetAttribute(edge_ws_kernel<128, 128, 512, 1>,
                         cudaFuncAttributeMaxDynamicSharedMemorySize, smemE3);

    int tilesN = (N + 127) / 128;
    int tilesE = (E + 127) / 128;              // 128-edge tiles
    int grid12 = tilesE < 296 ? tilesE : 296;  // 2 CTAs/SM
    int grid3  = tilesE < 148 ? tilesE : 148;  // 1 CTA/SM (512 thr)

    // layer 1 (h = pos)
    node_kernel<3, 64><<<tilesN, 256, smemN1>>>(pos, pos, w1a, b1a, Abuf, N);
    edge_ws_kernel<64, 64, 256, 2><<<grid12, 256, smemE12>>>(
        Abuf, pos, srcp, w1a + 3 * 64, w1b, b1b, h1, N, E, tilesE);
    // layer 2
    node_kernel<64, 64><<<tilesN, 256, smemN2>>>(h1, pos, w2a, b2a, Abuf, N);
    edge_ws_kernel<64, 64, 256, 2><<<grid12, 256, smemE12>>>(
        Abuf, pos, srcp, w2a + 64 * 64, w2b, b2b, h2, N, E, tilesE);
    // layer 3
    node_kernel<64, 128><<<tilesN, 256, smemN3>>>(h2, pos, w3a, b3a, Abuf, N);
    edge_ws_kernel<128, 128, 512, 1><<<grid3, 512, smemE3>>>(
        Abuf, pos, srcp, w3a + 64 * 128, w3b, b3b, h3, N, E, tilesE);
    // pool + regressor
    pool1_kernel<<<dim3(B, 8), 128>>>(h3, batch, N, part);
    pool2_kernel<<<B, 128>>>(part, batch, N, pl);
    reg_kernel<<<1, 64>>>(pl, wr1, br1, wr2, br2, out, B);
}

// round 11
// speedup vs baseline: 1.8792x; 1.2771x over previous
#include <cuda_runtime.h>
#include <cuda_bf16.h>
#include <cstdint>
#include <math.h>

// ---------------------------------------------------------------------------
// BackbonePointNet on GB300, round 11. Warp-specialized HMMA edge kernel
// (R10 structure) with 2-TERM split: X rounded once to bf16 (Xh), W kept as
// bf16 hi+lo => C = Xh@Wh + Xh@Wl = Xh@W. Error = X rounding only (~6e-4 RMS
// per element), attenuated by mean-pool over ~1560 nodes => final ~1e-4.
// vs R10: producer convert halved, MMAs 3->2 per kc, X smem halved
// (layers 1/2 now 3 CTAs/SM).
// ---------------------------------------------------------------------------

#define MAXN 100000
__device__ float g_A[MAXN * 128];
__device__ float g_h1[MAXN * 64];
__device__ float g_h2[MAXN * 64];
__device__ float g_h3[MAXN * 128];
__device__ float g_part[64 * 8 * 128];
__device__ float g_pool[64 * 128];

// --------------------------- small asm helpers ------------------------------
__device__ __forceinline__ void mma16816(float* c, const uint32_t* a,
                                         uint32_t b0, uint32_t b1) {
    asm volatile(
        "mma.sync.aligned.m16n8k16.row.col.f32.bf16.bf16.f32 "
        "{%0,%1,%2,%3}, {%4,%5,%6,%7}, {%8,%9}, {%0,%1,%2,%3};"
        : "+f"(c[0]), "+f"(c[1]), "+f"(c[2]), "+f"(c[3])
        : "r"(a[0]), "r"(a[1]), "r"(a[2]), "r"(a[3]), "r"(b0), "r"(b1));
}

// relu(a-p) for a pair -> packed bf16x2 (single rounding).
__device__ __forceinline__ uint32_t cvt_hi(float a0, float a1, float p0, float p1) {
    float x0 = fmaxf(a0 - p0, 0.f), x1 = fmaxf(a1 - p1, 0.f);
    uint32_t h;
    asm("cvt.rn.bf16x2.f32 %0, %1, %2;" : "=r"(h) : "f"(x1), "f"(x0));
    return h;
}

__device__ __forceinline__ unsigned long long pk2(float lo, float hi) {
    unsigned long long d;
    asm("mov.b64 %0, {%1, %2};" : "=l"(d)
        : "r"(__float_as_uint(lo)), "r"(__float_as_uint(hi)));
    return d;
}
__device__ __forceinline__ void upk2(unsigned long long v, float& lo, float& hi) {
    unsigned int a, b;
    asm("mov.b64 {%0, %1}, %2;" : "=r"(a), "=r"(b) : "l"(v));
    lo = __uint_as_float(a);
    hi = __uint_as_float(b);
}
__device__ __forceinline__ unsigned long long ffma2(unsigned long long a,
                                                    unsigned long long b,
                                                    unsigned long long c) {
    unsigned long long d;
    asm("fma.rn.f32x2 %0, %1, %2, %3;" : "=l"(d) : "l"(a), "l"(b), "l"(c));
    return d;
}

// ---------------------------------------------------------------------------
// Per-node GEMM1 (fp32 SIMT): A[n] = hin[n]@Wa[0:HC] + pos[n]@Wa_p + ba
// ---------------------------------------------------------------------------
template <int HC, int H>
__global__ __launch_bounds__(256)
void node_kernel(const float* __restrict__ hin, const float* __restrict__ pos,
                 const float* __restrict__ Wa, const float* __restrict__ ba,
                 float* __restrict__ A, int N) {
    constexpr int CIN  = HC + 3;
    constexpr int CINP = (CIN + 3) & ~3;
    extern __shared__ float sm[];
    float* Xs = sm;
    float* Ws = Xs + 128 * CINP;
    const int tid = threadIdx.x;
    const int n0  = blockIdx.x * 128;

    for (int idx = tid; idx < CINP * H; idx += 256) {
        int k = idx / H, c = idx - k * H;
        Ws[idx] = (k < CIN) ? Wa[k * H + c] : 0.f;
    }
    for (int idx = tid; idx < 128 * CINP; idx += 256) {
        int r = idx / CINP, k = idx - r * CINP;
        int n = n0 + r;
        float v = 0.f;
        if (n < N) {
            if (k < HC) v = hin[n * HC + k];
            else if (k < CIN) v = pos[n * 3 + (k - HC)];
        }
        Xs[idx] = v;
    }
    __syncthreads();

    const int tx = tid & 15, ty = tid >> 4;
    for (int cb = 0; cb < H; cb += 64) {
        unsigned long long acc[8][2];
#pragma unroll
        for (int j = 0; j < 2; ++j) {
            unsigned long long bv =
                *(const unsigned long long*)(ba + cb + 2 * (tx + 16 * j));
#pragma unroll
            for (int i = 0; i < 8; ++i) acc[i][j] = bv;
        }
#pragma unroll 4
        for (int k = 0; k < CINP; ++k) {
            unsigned long long w0 =
                *(const unsigned long long*)(Ws + k * H + cb + 2 * tx);
            unsigned long long w1 =
                *(const unsigned long long*)(Ws + k * H + cb + 2 * (tx + 16));
#pragma unroll
            for (int i = 0; i < 8; ++i) {
                float x = Xs[(ty + 16 * i) * CINP + k];
                unsigned long long xp = pk2(x, x);
                acc[i][0] = ffma2(xp, w0, acc[i][0]);
                acc[i][1] = ffma2(xp, w1, acc[i][1]);
            }
        }
#pragma unroll
        for (int i = 0; i < 8; ++i) {
            int n = n0 + ty + 16 * i;
            if (n < N) {
#pragma unroll
                for (int j = 0; j < 2; ++j) {
                    float lo, hi;
                    upk2(acc[i][j], lo, hi);
                    *(float2*)(A + n * H + cb + 2 * (tx + 16 * j)) =
                        make_float2(lo, hi);
                }
            }
        }
    }
}

// ---------------------------------------------------------------------------
// Warp-specialized edge kernel, 2-term split. Tile = 128 edges = 8 nodes.
// Producers: gather A, relu(A-P), bf16 round, STS. Consumers: A-frag LDS,
// 2 MMAs/kc (Wh chain + Wl chain), fragment seg-max. X double-buffered.
// ---------------------------------------------------------------------------
template <int H, int COUT, int TPB, int MAXB>
__global__ __launch_bounds__(TPB, MAXB)
void edge_ws_kernel(const float* __restrict__ A, const float* __restrict__ pos,
                    const int* __restrict__ src, const float* __restrict__ Wap,
                    const float* __restrict__ Wb, const float* __restrict__ bb,
                    float* __restrict__ hout, int N, int E, int tiles) {
    constexpr int WARPS = TPB / 32;
    constexpr int PW    = WARPS / 2;    // producer warps
    constexpr int NPN   = 8 / PW;       // nodes per warp (both roles)
    constexpr int KC    = H / 16;
    constexpr int NB    = COUT / 8;
    constexpr int RS    = H * 2 + 16;   // X row bytes (bf16 + pad)
    constexpr int SX    = H + 8;        // W padded row (bf16 elems)

    extern __shared__ char smem[];
    char* Xb[2] = {smem, smem + 128 * RS};
    __nv_bfloat16* Wh = (__nv_bfloat16*)(smem + 2 * 128 * RS);
    __nv_bfloat16* Wl = Wh + COUT * SX;

    const int tid = threadIdx.x, wid = tid >> 5, lane = tid & 31;
    const int r = lane >> 2, q = lane & 3;
    const bool isProd = wid < PW;

    // Stage W once (all threads). Wb gmem layout [H][COUT].
    for (int idx = tid; idx < H * COUT; idx += TPB) {
        int k = idx / COUT, n = idx - k * COUT;
        float w = Wb[idx];
        __nv_bfloat16 hb = __float2bfloat16(w);
        __nv_bfloat16 lb = __float2bfloat16(w - __bfloat162float(hb));
        Wh[n * SX + k] = hb;
        Wl[n * SX + k] = lb;
    }

    // ---- producer: fill Xbuf with tile t ----
    auto produce = [&](int t, char* Xbuf) {
        const int e0 = t * 128, n0t = t * 8;
        const int pw = wid;
#pragma unroll
        for (int nn = 0; nn < NPN; ++nn) {
            const int g  = pw * NPN + nn;           // node slot 0..7
            const int nd = min(n0t + g, N - 1);
            int e = e0 + 16 * g + (lane & 15);
            int srcv = (e < E) ? src[e] : 0;
            const int c4 = (H == 64) ? (lane & 15) : lane;
            float p0 = pos[nd * 3], p1 = pos[nd * 3 + 1], p2 = pos[nd * 3 + 2];
            float4 P;
            P.x = p0 * __ldg(&Wap[4 * c4 + 0]) + p1 * __ldg(&Wap[H + 4 * c4 + 0]) +
                  p2 * __ldg(&Wap[2 * H + 4 * c4 + 0]);
            P.y = p0 * __ldg(&Wap[4 * c4 + 1]) + p1 * __ldg(&Wap[H + 4 * c4 + 1]) +
                  p2 * __ldg(&Wap[2 * H + 4 * c4 + 1]);
            P.z = p0 * __ldg(&Wap[4 * c4 + 2]) + p1 * __ldg(&Wap[H + 4 * c4 + 2]) +
                  p2 * __ldg(&Wap[2 * H + 4 * c4 + 2]);
            P.w = p0 * __ldg(&Wap[4 * c4 + 3]) + p1 * __ldg(&Wap[H + 4 * c4 + 3]) +
                  p2 * __ldg(&Wap[2 * H + 4 * c4 + 3]);
            constexpr int PASSES = (H == 64) ? 8 : 16;
#pragma unroll
            for (int p = 0; p < PASSES; ++p) {
                int rowin = (H == 64) ? (2 * p + (lane >> 4)) : p;  // 0..15
                int j = __shfl_sync(0xffffffffu, srcv, rowin);
                const float4 a = ((const float4*)(A + (size_t)j * H))[c4];
                uint32_t h01 = cvt_hi(a.x, a.y, P.x, P.y);
                uint32_t h23 = cvt_hi(a.z, a.w, P.z, P.w);
                int row = 16 * g + rowin;
                *(uint2*)(Xbuf + row * RS + c4 * 8) = make_uint2(h01, h23);
            }
        }
    };

    // ---- consumer: MMA + seg-max for tile t ----
    auto consume = [&](int t, const char* Xbuf) {
        const int n0t = t * 8;
        const int cw  = wid - PW;

        uint32_t ah[NPN][KC][4];
#pragma unroll
        for (int nn = 0; nn < NPN; ++nn) {
            const int Rb = 16 * (cw * NPN + nn);
#pragma unroll
            for (int kc = 0; kc < KC; ++kc) {
#pragma unroll
                for (int pr = 0; pr < 4; ++pr) {
                    int row = Rb + r + 8 * (pr & 1);
                    int off = 32 * kc + 4 * q + 16 * (pr >> 1);
                    ah[nn][kc][pr] = *(const uint32_t*)(Xbuf + row * RS + off);
                }
            }
        }

        uint32_t bf[2][4];
        {
            size_t o0 = ((size_t)r * SX + 2 * q) * 2;
            bf[0][0] = *(const uint32_t*)((const char*)Wh + o0);
            bf[0][1] = *(const uint32_t*)((const char*)Wh + o0 + 16);
            bf[0][2] = *(const uint32_t*)((const char*)Wl + o0);
            bf[0][3] = *(const uint32_t*)((const char*)Wl + o0 + 16);
        }
#pragma unroll
        for (int nb = 0; nb < NB; ++nb) {
            float acc[NPN][2][4];
#pragma unroll
            for (int nn = 0; nn < NPN; ++nn)
#pragma unroll
                for (int ch = 0; ch < 2; ++ch)
#pragma unroll
                    for (int i = 0; i < 4; ++i) acc[nn][ch][i] = 0.f;
#pragma unroll
            for (int kc = 0; kc < KC; ++kc) {
                const int cur = (nb * KC + kc) & 1;
                {
                    int nnb = nb, nkc = kc + 1;
                    if (nkc == KC) { nkc = 0; nnb = (nb + 1 < NB) ? nb + 1 : nb; }
                    int wn = 8 * nnb + r;
                    size_t o0 = ((size_t)wn * SX + nkc * 16 + 2 * q) * 2;
                    bf[cur ^ 1][0] = *(const uint32_t*)((const char*)Wh + o0);
                    bf[cur ^ 1][1] = *(const uint32_t*)((const char*)Wh + o0 + 16);
                    bf[cur ^ 1][2] = *(const uint32_t*)((const char*)Wl + o0);
                    bf[cur ^ 1][3] = *(const uint32_t*)((const char*)Wl + o0 + 16);
                }
                const uint32_t* b = bf[cur];
#pragma unroll
                for (int nn = 0; nn < NPN; ++nn) {
                    mma16816(acc[nn][0], ah[nn][kc], b[0], b[1]);  // Wh chain
                    mma16816(acc[nn][1], ah[nn][kc], b[2], b[3]);  // Wl chain
                }
            }
#pragma unroll
            for (int nn = 0; nn < NPN; ++nn) {
                float s0 = acc[nn][0][0] + acc[nn][1][0];
                float s1 = acc[nn][0][1] + acc[nn][1][1];
                float s2 = acc[nn][0][2] + acc[nn][1][2];
                float s3 = acc[nn][0][3] + acc[nn][1][3];
                float m0 = fmaxf(s0, s2);
                float m1 = fmaxf(s1, s3);
                m0 = fmaxf(m0, __shfl_xor_sync(0xffffffffu, m0, 4));
                m1 = fmaxf(m1, __shfl_xor_sync(0xffffffffu, m1, 4));
                m0 = fmaxf(m0, __shfl_xor_sync(0xffffffffu, m0, 8));
                m1 = fmaxf(m1, __shfl_xor_sync(0xffffffffu, m1, 8));
                m0 = fmaxf(m0, __shfl_xor_sync(0xffffffffu, m0, 16));
                m1 = fmaxf(m1, __shfl_xor_sync(0xffffffffu, m1, 16));
                int node = n0t + cw * NPN + nn;
                if (lane < 4 && node < N) {
                    int col = 8 * nb + 2 * lane;
                    float2 o;
                    o.x = fmaxf(m0 + __ldg(&bb[col]), 0.f);
                    o.y = fmaxf(m1 + __ldg(&bb[col + 1]), 0.f);
                    *(float2*)(hout + (size_t)node * COUT + col) = o;
                }
            }
        }
    };

    __syncthreads();  // W staged

    const int t0 = blockIdx.x;  // grid <= tiles guaranteed by launcher
    if (isProd) produce(t0, Xb[0]);
    __syncthreads();

    for (int k = 0;; ++k) {
        int tc = t0 + k * gridDim.x;
        if (tc >= tiles) break;  // uniform across CTA
        if (isProd) {
            int tp = tc + gridDim.x;
            if (tp < tiles) produce(tp, Xb[(k + 1) & 1]);
        } else {
            consume(tc, Xb[k & 1]);
        }
        __syncthreads();
    }
}

// ---------------------------------------------------------------------------
// Deterministic two-stage mean pool (batch sorted) + regressor.
// ---------------------------------------------------------------------------
__device__ __forceinline__ int lb(const int* __restrict__ b, int n, int v) {
    int lo = 0, hi = n;
    while (lo < hi) {
        int m = (lo + hi) >> 1;
        if (b[m] < v) lo = m + 1; else hi = m;
    }
    return lo;
}

__global__ void pool1_kernel(const float* __restrict__ h3,
                             const int* __restrict__ batch, int N,
                             float* __restrict__ part) {
    int b = blockIdx.x, k = blockIdx.y, c = threadIdx.x;
    int s = lb(batch, N, b), e = lb(batch, N, b + 1);
    int len = e - s;
    int cs = s + (int)(((long long)len * k) >> 3);
    int ce = s + (int)(((long long)len * (k + 1)) >> 3);
    float s0 = 0.f, s1 = 0.f, s2 = 0.f, s3 = 0.f;
    int n = cs;
    for (; n + 3 < ce; n += 4) {
        s0 += h3[(n + 0) * 128 + c];
        s1 += h3[(n + 1) * 128 + c];
        s2 += h3[(n + 2) * 128 + c];
        s3 += h3[(n + 3) * 128 + c];
    }
    for (; n < ce; ++n) s0 += h3[n * 128 + c];
    part[(b * 8 + k) * 128 + c] = ((s0 + s1) + (s2 + s3));
}

__global__ void pool2_kernel(const float* __restrict__ part,
                             const int* __restrict__ batch, int N,
                             float* __restrict__ pool) {
    int b = blockIdx.x, c = threadIdx.x;
    int s = lb(batch, N, b), e = lb(batch, N, b + 1);
    float sum = 0.f;
#pragma unroll
    for (int k = 0; k < 8; ++k) sum += part[(b * 8 + k) * 128 + c];
    pool[b * 128 + c] = sum / fmaxf((float)(e - s), 1.f);
}

__global__ void reg_kernel(const float* __restrict__ pool,
                           const float* __restrict__ wr1, const float* __restrict__ br1,
                           const float* __restrict__ wr2, const float* __restrict__ br2,
                           float* __restrict__ out, int B) {
    int b = blockIdx.x * blockDim.x + threadIdx.x;
    if (b >= B) return;
    float o = br2[0];
    for (int j = 0; j < 64; ++j) {
        float s = br1[j];
        for (int k = 0; k < 128; ++k) s += pool[b * 128 + k] * wr1[k * 64 + j];
        o += s * wr2[j];
    }
    out[b] = 1.f / (1.f + expf(-o));
}

extern "C" void kernel_launch(void* const* d_in, const int* in_sizes, int n_in,
                              void* d_out, int out_size) {
    const float* pos   = (const float*)d_in[0];
    const int*   ei    = (const int*)d_in[1];
    const int*   batch = (const int*)d_in[2];
    const float* w1a = (const float*)d_in[4],  *b1a = (const float*)d_in[5];
    const float* w1b = (const float*)d_in[6],  *b1b = (const float*)d_in[7];
    const float* w2a = (const float*)d_in[8],  *b2a = (const float*)d_in[9];
    const float* w2b = (const float*)d_in[10], *b2b = (const float*)d_in[11];
    const float* w3a = (const float*)d_in[12], *b3a = (const float*)d_in[13];
    const float* w3b = (const float*)d_in[14], *b3b = (const float*)d_in[15];
    const float* wr1 = (const float*)d_in[16], *br1 = (const float*)d_in[17];
    const float* wr2 = (const float*)d_in[18], *br2 = (const float*)d_in[19];
    float* out = (float*)d_out;

    int N = in_sizes[0] / 3;
    int E = in_sizes[1] / 2;
    int B = out_size;
    const int* srcp = ei;

    float *Abuf, *h1, *h2, *h3, *part, *pl;
    cudaGetSymbolAddress((void**)&Abuf, g_A);
    cudaGetSymbolAddress((void**)&h1, g_h1);
    cudaGetSymbolAddress((void**)&h2, g_h2);
    cudaGetSymbolAddress((void**)&h3, g_h3);
    cudaGetSymbolAddress((void**)&part, g_part);
    cudaGetSymbolAddress((void**)&pl, g_pool);

    const int smemN1 = (128 * 8 + 8 * 64) * 4;
    const int smemN2 = (128 * 68 + 68 * 64) * 4;
    const int smemN3 = (128 * 68 + 68 * 128) * 4;
    // edge_ws: 2 X bufs (128 rows x RS) + W hi/lo
    const int smemE12 = 2 * 128 * (64 * 2 + 16) + 2 * 64 * 72 * 2;    //  55296
    const int smemE3  = 2 * 128 * (128 * 2 + 16) + 2 * 128 * 136 * 2; // 139264

    cudaFuncSetAttribute(node_kernel<3, 64>,
                         cudaFuncAttributeMaxDynamicSharedMemorySize, smemN1);
    cudaFuncSetAttribute(node_kernel<64, 64>,
                         cudaFuncAttributeMaxDynamicSharedMemorySize, smemN2);
    cudaFuncSetAttribute(node_kernel<64, 128>,
                         cudaFuncAttributeMaxDynamicSharedMemorySize, smemN3);
    cudaFuncSetAttribute(edge_ws_kernel<64, 64, 256, 3>,
                         cudaFuncAttributeMaxDynamicSharedMemorySize, smemE12);
    cudaFuncSetAttribute(edge_ws_kernel<128, 128, 512, 1>,
                         cudaFuncAttributeMaxDynamicSharedMemorySize, smemE3);

    int tilesN = (N + 127) / 128;
    int tilesE = (E + 127) / 128;              // 128-edge tiles
    int grid12 = tilesE < 444 ? tilesE : 444;  // 3 CTAs/SM
    int grid3  = tilesE < 148 ? tilesE : 148;  // 1 CTA/SM (512 thr)

    // layer 1 (h = pos)
    node_kernel<3, 64><<<tilesN, 256, smemN1>>>(pos, pos, w1a, b1a, Abuf, N);
    edge_ws_kernel<64, 64, 256, 3><<<grid12, 256, smemE12>>>(
        Abuf, pos, srcp, w1a + 3 * 64, w1b, b1b, h1, N, E, tilesE);
    // layer 2
    node_kernel<64, 64><<<tilesN, 256, smemN2>>>(h1, pos, w2a, b2a, Abuf, N);
    edge_ws_kernel<64, 64, 256, 3><<<grid12, 256, smemE12>>>(
        Abuf, pos, srcp, w2a + 64 * 64, w2b, b2b, h2, N, E, tilesE);
    // layer 3
    node_kernel<64, 128><<<tilesN, 256, smemN3>>>(h2, pos, w3a, b3a, Abuf, N);
    edge_ws_kernel<128, 128, 512, 1><<<grid3, 512, smemE3>>>(
        Abuf, pos, srcp, w3a + 64 * 128, w3b, b3b, h3, N, E, tilesE);
    // pool + regressor
    pool1_kernel<<<dim3(B, 8), 128>>>(h3, batch, N, part);
    pool2_kernel<<<B, 128>>>(part, batch, N, pl);
    reg_kernel<<<1, 64>>>(pl, wr1, br1, wr2, br2, out, B);
}

// round 12
// speedup vs baseline: 2.0489x; 1.0903x over previous
#include <cuda_runtime.h>
#include <cuda_bf16.h>
#include <cstdint>
#include <math.h>

// ---------------------------------------------------------------------------
// BackbonePointNet on GB300, round 12.
// Warp-specialized HMMA engine (R11, 2-term split: X bf16-rounded once, W as
// bf16 hi+lo) now used for BOTH the edge GEMM and the node GEMMs:
//  - node: A = [h, pos, 1, pad] @ [Wa_h; Wa_p; ba; 0]  (bias/pos folded in K)
//  - edge: C2 = bf16(relu(A[src]-P)) @ Wb, fragment-local 16-edge seg-max
//  - edge layer3 tiles widened to 256 edges (NPN=2) to double B-frag reuse.
// ---------------------------------------------------------------------------

#define MAXN 100000
__device__ float g_A[MAXN * 128];
__device__ float g_h1[MAXN * 64];
__device__ float g_h2[MAXN * 64];
__device__ float g_h3[MAXN * 128];
__device__ float g_part[64 * 8 * 128];
__device__ float g_pool[64 * 128];

// --------------------------- small asm helpers ------------------------------
__device__ __forceinline__ void mma16816(float* c, const uint32_t* a,
                                         uint32_t b0, uint32_t b1) {
    asm volatile(
        "mma.sync.aligned.m16n8k16.row.col.f32.bf16.bf16.f32 "
        "{%0,%1,%2,%3}, {%4,%5,%6,%7}, {%8,%9}, {%0,%1,%2,%3};"
        : "+f"(c[0]), "+f"(c[1]), "+f"(c[2]), "+f"(c[3])
        : "r"(a[0]), "r"(a[1]), "r"(a[2]), "r"(a[3]), "r"(b0), "r"(b1));
}

__device__ __forceinline__ uint32_t cvt_hi(float a0, float a1, float p0, float p1) {
    float x0 = fmaxf(a0 - p0, 0.f), x1 = fmaxf(a1 - p1, 0.f);
    uint32_t h;
    asm("cvt.rn.bf16x2.f32 %0, %1, %2;" : "=r"(h) : "f"(x1), "f"(x0));
    return h;
}
__device__ __forceinline__ uint32_t pack_bf16(float a0, float a1) {
    uint32_t h;
    asm("cvt.rn.bf16x2.f32 %0, %1, %2;" : "=r"(h) : "f"(a1), "f"(a0));
    return h;
}

__device__ __forceinline__ unsigned long long pk2(float lo, float hi) {
    unsigned long long d;
    asm("mov.b64 %0, {%1, %2};" : "=l"(d)
        : "r"(__float_as_uint(lo)), "r"(__float_as_uint(hi)));
    return d;
}
__device__ __forceinline__ void upk2(unsigned long long v, float& lo, float& hi) {
    unsigned int a, b;
    asm("mov.b64 {%0, %1}, %2;" : "=r"(a), "=r"(b) : "l"(v));
    lo = __uint_as_float(a);
    hi = __uint_as_float(b);
}
__device__ __forceinline__ unsigned long long ffma2(unsigned long long a,
                                                    unsigned long long b,
                                                    unsigned long long c) {
    unsigned long long d;
    asm("fma.rn.f32x2 %0, %1, %2, %3;" : "=l"(d) : "l"(a), "l"(b), "l"(c));
    return d;
}

// ---------------------------------------------------------------------------
// Layer-1 node GEMM (K=6, tiny): fp32 SIMT (verified R2-R11).
// ---------------------------------------------------------------------------
template <int HC, int H>
__global__ __launch_bounds__(256)
void node_kernel(const float* __restrict__ hin, const float* __restrict__ pos,
                 const float* __restrict__ Wa, const float* __restrict__ ba,
                 float* __restrict__ A, int N) {
    constexpr int CIN  = HC + 3;
    constexpr int CINP = (CIN + 3) & ~3;
    extern __shared__ float sm[];
    float* Xs = sm;
    float* Ws = Xs + 128 * CINP;
    const int tid = threadIdx.x;
    const int n0  = blockIdx.x * 128;

    for (int idx = tid; idx < CINP * H; idx += 256) {
        int k = idx / H, c = idx - k * H;
        Ws[idx] = (k < CIN) ? Wa[k * H + c] : 0.f;
    }
    for (int idx = tid; idx < 128 * CINP; idx += 256) {
        int r = idx / CINP, k = idx - r * CINP;
        int n = n0 + r;
        float v = 0.f;
        if (n < N) {
            if (k < HC) v = hin[n * HC + k];
            else if (k < CIN) v = pos[n * 3 + (k - HC)];
        }
        Xs[idx] = v;
    }
    __syncthreads();

    const int tx = tid & 15, ty = tid >> 4;
    for (int cb = 0; cb < H; cb += 64) {
        unsigned long long acc[8][2];
#pragma unroll
        for (int j = 0; j < 2; ++j) {
            unsigned long long bv =
                *(const unsigned long long*)(ba + cb + 2 * (tx + 16 * j));
#pragma unroll
            for (int i = 0; i < 8; ++i) acc[i][j] = bv;
        }
#pragma unroll 4
        for (int k = 0; k < CINP; ++k) {
            unsigned long long w0 =
                *(const unsigned long long*)(Ws + k * H + cb + 2 * tx);
            unsigned long long w1 =
                *(const unsigned long long*)(Ws + k * H + cb + 2 * (tx + 16));
#pragma unroll
            for (int i = 0; i < 8; ++i) {
                float x = Xs[(ty + 16 * i) * CINP + k];
                unsigned long long xp = pk2(x, x);
                acc[i][0] = ffma2(xp, w0, acc[i][0]);
                acc[i][1] = ffma2(xp, w1, acc[i][1]);
            }
        }
#pragma unroll
        for (int i = 0; i < 8; ++i) {
            int n = n0 + ty + 16 * i;
            if (n < N) {
#pragma unroll
                for (int j = 0; j < 2; ++j) {
                    float lo, hi;
                    upk2(acc[i][j], lo, hi);
                    *(float2*)(A + n * H + cb + 2 * (tx + 16 * j)) =
                        make_float2(lo, hi);
                }
            }
        }
    }
}

// ---------------------------------------------------------------------------
// Node GEMM via WS-HMMA: A[n] = [h, pos, 1, pad] @ [Wa; ba; 0] (K folded).
// Tile = 128 nodes. 4 producer + 4 consumer warps.
// ---------------------------------------------------------------------------
template <int HC, int H, int MAXB>
__global__ __launch_bounds__(256, MAXB)
void node_mma_kernel(const float* __restrict__ hin, const float* __restrict__ pos,
                     const float* __restrict__ Wa, const float* __restrict__ ba,
                     float* __restrict__ A, int N, int tiles) {
    constexpr int CIN = HC + 3;
    constexpr int KT  = ((HC + 4 + 15) / 16) * 16;  // 80 for HC=64
    constexpr int KC  = KT / 16;
    constexpr int RS  = KT * 2 + 16;   // X row bytes
    constexpr int SX  = KT + 8;        // W padded row (bf16)
    constexpr int NB  = H / 8;
    constexpr int PW  = 4;

    extern __shared__ char smem[];
    char* Xb[2] = {smem, smem + 128 * RS};
    __nv_bfloat16* Wh = (__nv_bfloat16*)(smem + 2 * 128 * RS);
    __nv_bfloat16* Wl = Wh + H * SX;

    const int tid = threadIdx.x, wid = tid >> 5, lane = tid & 31;
    const int r = lane >> 2, q = lane & 3;
    const bool isProd = wid < PW;

    // Stage Wtilde hi/lo: rows k<CIN from Wa, k==CIN = ba, else 0.
    for (int idx = tid; idx < KT * H; idx += 256) {
        int k = idx / H, c = idx - k * H;
        float w = (k < CIN) ? Wa[k * H + c] : ((k == CIN) ? ba[c] : 0.f);
        __nv_bfloat16 hb = __float2bfloat16(w);
        __nv_bfloat16 lb = __float2bfloat16(w - __bfloat162float(hb));
        Wh[c * SX + k] = hb;
        Wl[c * SX + k] = lb;
    }

    auto produce = [&](int t, char* Xbuf) {
        const int base = wid * 32;
        // h columns (HC=64 -> 16 quads), 2 rows per pass
#pragma unroll
        for (int p = 0; p < 16; ++p) {
            int row = base + 2 * p + (lane >> 4);
            int c4  = lane & 15;
            int n   = t * 128 + row;
            float4 a = make_float4(0.f, 0.f, 0.f, 0.f);
            if (n < N) a = ((const float4*)(hin + (size_t)n * HC))[c4];
            *(uint2*)(Xbuf + row * RS + c4 * 8) =
                make_uint2(pack_bf16(a.x, a.y), pack_bf16(a.z, a.w));
        }
        // tail quads: [pos0,pos1,pos2,1], then zeros
#pragma unroll
        for (int p = 0; p < (KT - HC) / 4; ++p) {
            int row = base + lane;
            int n   = t * 128 + row;
            float4 v = make_float4(0.f, 0.f, 0.f, 0.f);
            if (p == 0) {
                int nn = (n < N) ? n : (N - 1);
                v.x = pos[nn * 3]; v.y = pos[nn * 3 + 1]; v.z = pos[nn * 3 + 2];
                v.w = 1.f;
            }
            *(uint2*)(Xbuf + row * RS + (HC / 4 + p) * 8) =
                make_uint2(pack_bf16(v.x, v.y), pack_bf16(v.z, v.w));
        }
    };

    auto consume = [&](int t, const char* Xbuf) {
        const int cw = wid - PW;
        uint32_t ah[2][KC][4];
#pragma unroll
        for (int mt = 0; mt < 2; ++mt) {
            const int Rb = 16 * (cw * 2 + mt);
#pragma unroll
            for (int kc = 0; kc < KC; ++kc)
#pragma unroll
                for (int pr = 0; pr < 4; ++pr) {
                    int row = Rb + r + 8 * (pr & 1);
                    int off = 32 * kc + 4 * q + 16 * (pr >> 1);
                    ah[mt][kc][pr] = *(const uint32_t*)(Xbuf + row * RS + off);
                }
        }
        uint32_t bf[2][4];
        {
            size_t o0 = ((size_t)r * SX + 2 * q) * 2;
            bf[0][0] = *(const uint32_t*)((const char*)Wh + o0);
            bf[0][1] = *(const uint32_t*)((const char*)Wh + o0 + 16);
            bf[0][2] = *(const uint32_t*)((const char*)Wl + o0);
            bf[0][3] = *(const uint32_t*)((const char*)Wl + o0 + 16);
        }
#pragma unroll
        for (int nb = 0; nb < NB; ++nb) {
            float acc[2][2][4];
#pragma unroll
            for (int mt = 0; mt < 2; ++mt)
#pragma unroll
                for (int ch = 0; ch < 2; ++ch)
#pragma unroll
                    for (int i = 0; i < 4; ++i) acc[mt][ch][i] = 0.f;
#pragma unroll
            for (int kc = 0; kc < KC; ++kc) {
                const int cur = (nb * KC + kc) & 1;
                {
                    int nnb = nb, nkc = kc + 1;
                    if (nkc == KC) { nkc = 0; nnb = (nb + 1 < NB) ? nb + 1 : nb; }
                    int wn = 8 * nnb + r;
                    size_t o0 = ((size_t)wn * SX + nkc * 16 + 2 * q) * 2;
                    bf[cur ^ 1][0] = *(const uint32_t*)((const char*)Wh + o0);
                    bf[cur ^ 1][1] = *(const uint32_t*)((const char*)Wh + o0 + 16);
                    bf[cur ^ 1][2] = *(const uint32_t*)((const char*)Wl + o0);
                    bf[cur ^ 1][3] = *(const uint32_t*)((const char*)Wl + o0 + 16);
                }
                const uint32_t* b = bf[cur];
#pragma unroll
                for (int mt = 0; mt < 2; ++mt) {
                    mma16816(acc[mt][0], ah[mt][kc], b[0], b[1]);
                    mma16816(acc[mt][1], ah[mt][kc], b[2], b[3]);
                }
            }
#pragma unroll
            for (int mt = 0; mt < 2; ++mt) {
                int nbase = t * 128 + 16 * (cw * 2 + mt);
                float2 v0 = make_float2(acc[mt][0][0] + acc[mt][1][0],
                                        acc[mt][0][1] + acc[mt][1][1]);
                float2 v1 = make_float2(acc[mt][0][2] + acc[mt][1][2],
                                        acc[mt][0][3] + acc[mt][1][3]);
                int col = 8 * nb + 2 * q;
                int nA = nbase + r, nBr = nbase + r + 8;
                if (nA < N)  *(float2*)(A + (size_t)nA * H + col) = v0;
                if (nBr < N) *(float2*)(A + (size_t)nBr * H + col) = v1;
            }
        }
    };

    __syncthreads();  // W staged
    const int t0 = blockIdx.x;
    if (isProd) produce(t0, Xb[0]);
    __syncthreads();

    for (int k = 0;; ++k) {
        int tc = t0 + k * gridDim.x;
        if (tc >= tiles) break;
        if (isProd) {
            int tp = tc + gridDim.x;
            if (tp < tiles) produce(tp, Xb[(k + 1) & 1]);
        } else {
            consume(tc, Xb[k & 1]);
        }
        __syncthreads();
    }
}

// ---------------------------------------------------------------------------
// Warp-specialized edge kernel, 2-term split. NODES = TPB/32 per tile
// (2 nodes per warp in each role). TPB=256: 8 nodes/128 edges (as R11);
// TPB=512: 16 nodes/256 edges (layer 3, doubles B-frag reuse).
// ---------------------------------------------------------------------------
template <int H, int COUT, int TPB, int MAXB>
__global__ __launch_bounds__(TPB, MAXB)
void edge_ws_kernel(const float* __restrict__ A, const float* __restrict__ pos,
                    const int* __restrict__ src, const float* __restrict__ Wap,
                    const float* __restrict__ Wb, const float* __restrict__ bb,
                    float* __restrict__ hout, int N, int E, int tiles) {
    constexpr int WARPS = TPB / 32;
    constexpr int PW    = WARPS / 2;
    constexpr int NPN   = 2;            // nodes per warp
    constexpr int NODES = PW * NPN;     // nodes per tile
    constexpr int ROWS  = NODES * 16;   // edges per tile
    constexpr int KC    = H / 16;
    constexpr int NB    = COUT / 8;
    constexpr int RS    = H * 2 + 16;   // X row bytes
    constexpr int SX    = H + 8;        // W padded row (bf16)

    extern __shared__ char smem[];
    char* Xb[2] = {smem, smem + ROWS * RS};
    __nv_bfloat16* Wh = (__nv_bfloat16*)(smem + 2 * ROWS * RS);
    __nv_bfloat16* Wl = Wh + COUT * SX;

    const int tid = threadIdx.x, wid = tid >> 5, lane = tid & 31;
    const int r = lane >> 2, q = lane & 3;
    const bool isProd = wid < PW;

    for (int idx = tid; idx < H * COUT; idx += TPB) {
        int k = idx / COUT, n = idx - k * COUT;
        float w = Wb[idx];
        __nv_bfloat16 hb = __float2bfloat16(w);
        __nv_bfloat16 lb = __float2bfloat16(w - __bfloat162float(hb));
        Wh[n * SX + k] = hb;
        Wl[n * SX + k] = lb;
    }

    auto produce = [&](int t, char* Xbuf) {
        const int e0 = t * ROWS, n0t = t * NODES;
        const int pw = wid;
#pragma unroll
        for (int nn = 0; nn < NPN; ++nn) {
            const int g  = pw * NPN + nn;
            const int nd = min(n0t + g, N - 1);
            int e = e0 + 16 * g + (lane & 15);
            int srcv = (e < E) ? src[e] : 0;
            const int c4 = (H == 64) ? (lane & 15) : lane;
            float p0 = pos[nd * 3], p1 = pos[nd * 3 + 1], p2 = pos[nd * 3 + 2];
            float4 P;
            P.x = p0 * __ldg(&Wap[4 * c4 + 0]) + p1 * __ldg(&Wap[H + 4 * c4 + 0]) +
                  p2 * __ldg(&Wap[2 * H + 4 * c4 + 0]);
            P.y = p0 * __ldg(&Wap[4 * c4 + 1]) + p1 * __ldg(&Wap[H + 4 * c4 + 1]) +
                  p2 * __ldg(&Wap[2 * H + 4 * c4 + 1]);
            P.z = p0 * __ldg(&Wap[4 * c4 + 2]) + p1 * __ldg(&Wap[H + 4 * c4 + 2]) +
                  p2 * __ldg(&Wap[2 * H + 4 * c4 + 2]);
            P.w = p0 * __ldg(&Wap[4 * c4 + 3]) + p1 * __ldg(&Wap[H + 4 * c4 + 3]) +
                  p2 * __ldg(&Wap[2 * H + 4 * c4 + 3]);
            constexpr int PASSES = (H == 64) ? 8 : 16;
#pragma unroll
            for (int p = 0; p < PASSES; ++p) {
                int rowin = (H == 64) ? (2 * p + (lane >> 4)) : p;
                int j = __shfl_sync(0xffffffffu, srcv, rowin);
                const float4 a = ((const float4*)(A + (size_t)j * H))[c4];
                uint32_t h01 = cvt_hi(a.x, a.y, P.x, P.y);
                uint32_t h23 = cvt_hi(a.z, a.w, P.z, P.w);
                int row = 16 * g + rowin;
                *(uint2*)(Xbuf + row * RS + c4 * 8) = make_uint2(h01, h23);
            }
        }
    };

    auto consume = [&](int t, const char* Xbuf) {
        const int n0t = t * NODES;
        const int cw  = wid - PW;

        uint32_t ah[NPN][KC][4];
#pragma unroll
        for (int nn = 0; nn < NPN; ++nn) {
            const int Rb = 16 * (cw * NPN + nn);
#pragma unroll
            for (int kc = 0; kc < KC; ++kc)
#pragma unroll
                for (int pr = 0; pr < 4; ++pr) {
                    int row = Rb + r + 8 * (pr & 1);
                    int off = 32 * kc + 4 * q + 16 * (pr >> 1);
                    ah[nn][kc][pr] = *(const uint32_t*)(Xbuf + row * RS + off);
                }
        }

        uint32_t bf[2][4];
        {
            size_t o0 = ((size_t)r * SX + 2 * q) * 2;
            bf[0][0] = *(const uint32_t*)((const char*)Wh + o0);
            bf[0][1] = *(const uint32_t*)((const char*)Wh + o0 + 16);
            bf[0][2] = *(const uint32_t*)((const char*)Wl + o0);
            bf[0][3] = *(const uint32_t*)((const char*)Wl + o0 + 16);
        }
#pragma unroll
        for (int nb = 0; nb < NB; ++nb) {
            float acc[NPN][2][4];
#pragma unroll
            for (int nn = 0; nn < NPN; ++nn)
#pragma unroll
                for (int ch = 0; ch < 2; ++ch)
#pragma unroll
                    for (int i = 0; i < 4; ++i) acc[nn][ch][i] = 0.f;
#pragma unroll
            for (int kc = 0; kc < KC; ++kc) {
                const int cur = (nb * KC + kc) & 1;
                {
                    int nnb = nb, nkc = kc + 1;
                    if (nkc == KC) { nkc = 0; nnb = (nb + 1 < NB) ? nb + 1 : nb; }
                    int wn = 8 * nnb + r;
                    size_t o0 = ((size_t)wn * SX + nkc * 16 + 2 * q) * 2;
                    bf[cur ^ 1][0] = *(const uint32_t*)((const char*)Wh + o0);
                    bf[cur ^ 1][1] = *(const uint32_t*)((const char*)Wh + o0 + 16);
                    bf[cur ^ 1][2] = *(const uint32_t*)((const char*)Wl + o0);
                    bf[cur ^ 1][3] = *(const uint32_t*)((const char*)Wl + o0 + 16);
                }
                const uint32_t* b = bf[cur];
#pragma unroll
                for (int nn = 0; nn < NPN; ++nn) {
                    mma16816(acc[nn][0], ah[nn][kc], b[0], b[1]);
                    mma16816(acc[nn][1], ah[nn][kc], b[2], b[3]);
                }
            }
#pragma unroll
            for (int nn = 0; nn < NPN; ++nn) {
                float s0 = acc[nn][0][0] + acc[nn][1][0];
                float s1 = acc[nn][0][1] + acc[nn][1][1];
                float s2 = acc[nn][0][2] + acc[nn][1][2];
                float s3 = acc[nn][0][3] + acc[nn][1][3];
                float m0 = fmaxf(s0, s2);
                float m1 = fmaxf(s1, s3);
                m0 = fmaxf(m0, __shfl_xor_sync(0xffffffffu, m0, 4));
                m1 = fmaxf(m1, __shfl_xor_sync(0xffffffffu, m1, 4));
                m0 = fmaxf(m0, __shfl_xor_sync(0xffffffffu, m0, 8));
                m1 = fmaxf(m1, __shfl_xor_sync(0xffffffffu, m1, 8));
                m0 = fmaxf(m0, __shfl_xor_sync(0xffffffffu, m0, 16));
                m1 = fmaxf(m1, __shfl_xor_sync(0xffffffffu, m1, 16));
                int node = n0t + cw * NPN + nn;
                if (lane < 4 && node < N) {
                    int col = 8 * nb + 2 * lane;
                    float2 o;
                    o.x = fmaxf(m0 + __ldg(&bb[col]), 0.f);
                    o.y = fmaxf(m1 + __ldg(&bb[col + 1]), 0.f);
                    *(float2*)(hout + (size_t)node * COUT + col) = o;
                }
            }
        }
    };

    __syncthreads();  // W staged
    const int t0 = blockIdx.x;
    if (isProd) produce(t0, Xb[0]);
    __syncthreads();

    for (int k = 0;; ++k) {
        int tc = t0 + k * gridDim.x;
        if (tc >= tiles) break;
        if (isProd) {
            int tp = tc + gridDim.x;
            if (tp < tiles) produce(tp, Xb[(k + 1) & 1]);
        } else {
            consume(tc, Xb[k & 1]);
        }
        __syncthreads();
    }
}

// ---------------------------------------------------------------------------
// Deterministic two-stage mean pool (batch sorted) + regressor.
// ---------------------------------------------------------------------------
__device__ __forceinline__ int lb(const int* __restrict__ b, int n, int v) {
    int lo = 0, hi = n;
    while (lo < hi) {
        int m = (lo + hi) >> 1;
        if (b[m] < v) lo = m + 1; else hi = m;
    }
    return lo;
}

__global__ void pool1_kernel(const float* __restrict__ h3,
                             const int* __restrict__ batch, int N,
                             float* __restrict__ part) {
    int b = blockIdx.x, k = blockIdx.y, c = threadIdx.x;
    int s = lb(batch, N, b), e = lb(batch, N, b + 1);
    int len = e - s;
    int cs = s + (int)(((long long)len * k) >> 3);
    int ce = s + (int)(((long long)len * (k + 1)) >> 3);
    float s0 = 0.f, s1 = 0.f, s2 = 0.f, s3 = 0.f;
    int n = cs;
    for (; n + 3 < ce; n += 4) {
        s0 += h3[(n + 0) * 128 + c];
        s1 += h3[(n + 1) * 128 + c];
        s2 += h3[(n + 2) * 128 + c];
        s3 += h3[(n + 3) * 128 + c];
    }
    for (; n < ce; ++n) s0 += h3[n * 128 + c];
    part[(b * 8 + k) * 128 + c] = ((s0 + s1) + (s2 + s3));
}

__global__ void pool2_kernel(const float* __restrict__ part,
                             const int* __restrict__ batch, int N,
                             float* __restrict__ pool) {
    int b = blockIdx.x, c = threadIdx.x;
    int s = lb(batch, N, b), e = lb(batch, N, b + 1);
    float sum = 0.f;
#pragma unroll
    for (int k = 0; k < 8; ++k) sum += part[(b * 8 + k) * 128 + c];
    pool[b * 128 + c] = sum / fmaxf((float)(e - s), 1.f);
}

__global__ void reg_kernel(const float* __restrict__ pool,
                           const float* __restrict__ wr1, const float* __restrict__ br1,
                           const float* __restrict__ wr2, const float* __restrict__ br2,
                           float* __restrict__ out, int B) {
    int b = blockIdx.x * blockDim.x + threadIdx.x;
    if (b >= B) return;
    float o = br2[0];
    for (int j = 0; j < 64; ++j) {
        float s = br1[j];
        for (int k = 0; k < 128; ++k) s += pool[b * 128 + k] * wr1[k * 64 + j];
        o += s * wr2[j];
    }
    out[b] = 1.f / (1.f + expf(-o));
}

extern "C" void kernel_launch(void* const* d_in, const int* in_sizes, int n_in,
                              void* d_out, int out_size) {
    const float* pos   = (const float*)d_in[0];
    const int*   ei    = (const int*)d_in[1];
    const int*   batch = (const int*)d_in[2];
    const float* w1a = (const float*)d_in[4],  *b1a = (const float*)d_in[5];
    const float* w1b = (const float*)d_in[6],  *b1b = (const float*)d_in[7];
    const float* w2a = (const float*)d_in[8],  *b2a = (const float*)d_in[9];
    const float* w2b = (const float*)d_in[10], *b2b = (const float*)d_in[11];
    const float* w3a = (const float*)d_in[12], *b3a = (const float*)d_in[13];
    const float* w3b = (const float*)d_in[14], *b3b = (const float*)d_in[15];
    const float* wr1 = (const float*)d_in[16], *br1 = (const float*)d_in[17];
    const float* wr2 = (const float*)d_in[18], *br2 = (const float*)d_in[19];
    float* out = (float*)d_out;

    int N = in_sizes[0] / 3;
    int E = in_sizes[1] / 2;
    int B = out_size;
    const int* srcp = ei;

    float *Abuf, *h1, *h2, *h3, *part, *pl;
    cudaGetSymbolAddress((void**)&Abuf, g_A);
    cudaGetSymbolAddress((void**)&h1, g_h1);
    cudaGetSymbolAddress((void**)&h2, g_h2);
    cudaGetSymbolAddress((void**)&h3, g_h3);
    cudaGetSymbolAddress((void**)&part, g_part);
    cudaGetSymbolAddress((void**)&pl, g_pool);

    const int smemN1 = (128 * 8 + 8 * 64) * 4;
    // node_mma: 2 X bufs (128 x RS=176) + W hi/lo (H x SX=88 bf16 x2)
    const int smemNM2 = 2 * 128 * 176 + 2 * 64 * 88 * 2;    //  67584
    const int smemNM3 = 2 * 128 * 176 + 2 * 128 * 88 * 2;   //  90112
    // edge_ws: 2 X bufs (ROWS x RS) + W hi/lo
    const int smemE12 = 2 * 128 * (64 * 2 + 16) + 2 * 64 * 72 * 2;    //  55296
    const int smemE3  = 2 * 256 * (128 * 2 + 16) + 2 * 128 * 136 * 2; // 208896

    cudaFuncSetAttribute(node_kernel<3, 64>,
                         cudaFuncAttributeMaxDynamicSharedMemorySize, smemN1);
    cudaFuncSetAttribute(node_mma_kernel<64, 64, 3>,
                         cudaFuncAttributeMaxDynamicSharedMemorySize, smemNM2);
    cudaFuncSetAttribute(node_mma_kernel<64, 128, 2>,
                         cudaFuncAttributeMaxDynamicSharedMemorySize, smemNM3);
    cudaFuncSetAttribute(edge_ws_kernel<64, 64, 256, 3>,
                         cudaFuncAttributeMaxDynamicSharedMemorySize, smemE12);
    cudaFuncSetAttribute(edge_ws_kernel<128, 128, 512, 1>,
                         cudaFuncAttributeMaxDynamicSharedMemorySize, smemE3);

    int tilesN = (N + 127) / 128;
    int tilesE12 = (E + 127) / 128;   // 128-edge tiles
    int tilesE3  = (E + 255) / 256;   // 256-edge tiles
    int gridN2 = tilesN < 444 ? tilesN : 444;
    int gridN3 = tilesN < 296 ? tilesN : 296;
    int grid12 = tilesE12 < 444 ? tilesE12 : 444;
    int grid3  = tilesE3 < 148 ? tilesE3 : 148;

    // layer 1 (h = pos)
    node_kernel<3, 64><<<tilesN, 256, smemN1>>>(pos, pos, w1a, b1a, Abuf, N);
    edge_ws_kernel<64, 64, 256, 3><<<grid12, 256, smemE12>>>(
        Abuf, pos, srcp, w1a + 3 * 64, w1b, b1b, h1, N, E, tilesE12);
    // layer 2
    node_mma_kernel<64, 64, 3><<<gridN2, 256, smemNM2>>>(
        h1, pos, w2a, b2a, Abuf, N, tilesN);
    edge_ws_kernel<64, 64, 256, 3><<<grid12, 256, smemE12>>>(
        Abuf, pos, srcp, w2a + 64 * 64, w2b, b2b, h2, N, E, tilesE12);
    // layer 3
    node_mma_kernel<64, 128, 2><<<gridN3, 256, smemNM3>>>(
        h2, pos, w3a, b3a, Abuf, N, tilesN);
    edge_ws_kernel<128, 128, 512, 1><<<grid3, 512, smemE3>>>(
        Abuf, pos, srcp, w3a + 64 * 128, w3b, b3b, h3, N, E, tilesE3);
    // pool + regressor
    pool1_kernel<<<dim3(B, 8), 128>>>(h3, batch, N, part);
    pool2_kernel<<<B, 128>>>(part, batch, N, pl);
    reg_kernel<<<1, 64>>>(pl, wr1, br1, wr2, br2, out, B);
}

// round 13
// speedup vs baseline: 2.1308x; 1.0400x over previous
#include <cuda_runtime.h>
#include <cuda_bf16.h>
#include <cstdint>
#include <math.h>

// ---------------------------------------------------------------------------
// BackbonePointNet on GB300, round 13 = R12 + ldmatrix fragment loads.
// R12 ncu: consumer issued >1 scalar LDS per MMA (L1 67%, tensor 36%).
// Fix: ldmatrix.m8n8.x4.b16 loads a whole A-frag (or Wh+Wl B-frags together)
// in ONE instruction -> ~7x fewer shared-load issues. Numerics unchanged.
// Engine (validated rel_err=0.0): 2-term bf16 split (X rounded once, W hi+lo),
// warp-specialized producer/consumer with double-buffered X tiles;
// node GEMMs fold pos+bias into K; edge seg-max inside the C fragment.
// ---------------------------------------------------------------------------

#define MAXN 100000
__device__ float g_A[MAXN * 128];
__device__ float g_h1[MAXN * 64];
__device__ float g_h2[MAXN * 64];
__device__ float g_h3[MAXN * 128];
__device__ float g_part[64 * 8 * 128];
__device__ float g_pool[64 * 128];

// --------------------------- small asm helpers ------------------------------
__device__ __forceinline__ void mma16816(float* c, const uint32_t* a,
                                         uint32_t b0, uint32_t b1) {
    asm volatile(
        "mma.sync.aligned.m16n8k16.row.col.f32.bf16.bf16.f32 "
        "{%0,%1,%2,%3}, {%4,%5,%6,%7}, {%8,%9}, {%0,%1,%2,%3};"
        : "+f"(c[0]), "+f"(c[1]), "+f"(c[2]), "+f"(c[3])
        : "r"(a[0]), "r"(a[1]), "r"(a[2]), "r"(a[3]), "r"(b0), "r"(b1));
}

__device__ __forceinline__ void ldsm_x4(uint32_t* d, uint32_t addr) {
    asm volatile(
        "ldmatrix.sync.aligned.m8n8.x4.shared.b16 {%0,%1,%2,%3}, [%4];"
        : "=r"(d[0]), "=r"(d[1]), "=r"(d[2]), "=r"(d[3]) : "r"(addr));
}

__device__ __forceinline__ uint32_t smem_u32(const void* p) {
    uint32_t a;
    asm("{ .reg .u64 t; cvta.to.shared.u64 t, %1; cvt.u32.u64 %0, t; }"
        : "=r"(a) : "l"(p));
    return a;
}

__device__ __forceinline__ uint32_t cvt_hi(float a0, float a1, float p0, float p1) {
    float x0 = fmaxf(a0 - p0, 0.f), x1 = fmaxf(a1 - p1, 0.f);
    uint32_t h;
    asm("cvt.rn.bf16x2.f32 %0, %1, %2;" : "=r"(h) : "f"(x1), "f"(x0));
    return h;
}
__device__ __forceinline__ uint32_t pack_bf16(float a0, float a1) {
    uint32_t h;
    asm("cvt.rn.bf16x2.f32 %0, %1, %2;" : "=r"(h) : "f"(a1), "f"(a0));
    return h;
}

__device__ __forceinline__ unsigned long long pk2(float lo, float hi) {
    unsigned long long d;
    asm("mov.b64 %0, {%1, %2};" : "=l"(d)
        : "r"(__float_as_uint(lo)), "r"(__float_as_uint(hi)));
    return d;
}
__device__ __forceinline__ void upk2(unsigned long long v, float& lo, float& hi) {
    unsigned int a, b;
    asm("mov.b64 {%0, %1}, %2;" : "=r"(a), "=r"(b) : "l"(v));
    lo = __uint_as_float(a);
    hi = __uint_as_float(b);
}
__device__ __forceinline__ unsigned long long ffma2(unsigned long long a,
                                                    unsigned long long b,
                                                    unsigned long long c) {
    unsigned long long d;
    asm("fma.rn.f32x2 %0, %1, %2, %3;" : "=l"(d) : "l"(a), "l"(b), "l"(c));
    return d;
}

// ---------------------------------------------------------------------------
// Layer-1 node GEMM (K=6, tiny): fp32 SIMT.
// ---------------------------------------------------------------------------
template <int HC, int H>
__global__ __launch_bounds__(256)
void node_kernel(const float* __restrict__ hin, const float* __restrict__ pos,
                 const float* __restrict__ Wa, const float* __restrict__ ba,
                 float* __restrict__ A, int N) {
    constexpr int CIN  = HC + 3;
    constexpr int CINP = (CIN + 3) & ~3;
    extern __shared__ float sm[];
    float* Xs = sm;
    float* Ws = Xs + 128 * CINP;
    const int tid = threadIdx.x;
    const int n0  = blockIdx.x * 128;

    for (int idx = tid; idx < CINP * H; idx += 256) {
        int k = idx / H, c = idx - k * H;
        Ws[idx] = (k < CIN) ? Wa[k * H + c] : 0.f;
    }
    for (int idx = tid; idx < 128 * CINP; idx += 256) {
        int r = idx / CINP, k = idx - r * CINP;
        int n = n0 + r;
        float v = 0.f;
        if (n < N) {
            if (k < HC) v = hin[n * HC + k];
            else if (k < CIN) v = pos[n * 3 + (k - HC)];
        }
        Xs[idx] = v;
    }
    __syncthreads();

    const int tx = tid & 15, ty = tid >> 4;
    for (int cb = 0; cb < H; cb += 64) {
        unsigned long long acc[8][2];
#pragma unroll
        for (int j = 0; j < 2; ++j) {
            unsigned long long bv =
                *(const unsigned long long*)(ba + cb + 2 * (tx + 16 * j));
#pragma unroll
            for (int i = 0; i < 8; ++i) acc[i][j] = bv;
        }
#pragma unroll 4
        for (int k = 0; k < CINP; ++k) {
            unsigned long long w0 =
                *(const unsigned long long*)(Ws + k * H + cb + 2 * tx);
            unsigned long long w1 =
                *(const unsigned long long*)(Ws + k * H + cb + 2 * (tx + 16));
#pragma unroll
            for (int i = 0; i < 8; ++i) {
                float x = Xs[(ty + 16 * i) * CINP + k];
                unsigned long long xp = pk2(x, x);
                acc[i][0] = ffma2(xp, w0, acc[i][0]);
                acc[i][1] = ffma2(xp, w1, acc[i][1]);
            }
        }
#pragma unroll
        for (int i = 0; i < 8; ++i) {
            int n = n0 + ty + 16 * i;
            if (n < N) {
#pragma unroll
                for (int j = 0; j < 2; ++j) {
                    float lo, hi;
                    upk2(acc[i][j], lo, hi);
                    *(float2*)(A + n * H + cb + 2 * (tx + 16 * j)) =
                        make_float2(lo, hi);
                }
            }
        }
    }
}

// ---------------------------------------------------------------------------
// Node GEMM via WS-HMMA: A[n] = [h, pos, 1, pad] @ [Wa; ba; 0] (K folded).
// ---------------------------------------------------------------------------
template <int HC, int H, int MAXB>
__global__ __launch_bounds__(256, MAXB)
void node_mma_kernel(const float* __restrict__ hin, const float* __restrict__ pos,
                     const float* __restrict__ Wa, const float* __restrict__ ba,
                     float* __restrict__ A, int N, int tiles) {
    constexpr int CIN = HC + 3;
    constexpr int KT  = ((HC + 4 + 15) / 16) * 16;  // 80 for HC=64
    constexpr int KC  = KT / 16;
    constexpr int RS  = KT * 2 + 16;   // X row bytes
    constexpr int SX  = KT + 8;        // W padded row (bf16)
    constexpr int NB  = H / 8;
    constexpr int PW  = 4;

    extern __shared__ char smem[];
    char* Xb[2] = {smem, smem + 128 * RS};
    __nv_bfloat16* Wh = (__nv_bfloat16*)(smem + 2 * 128 * RS);
    __nv_bfloat16* Wl = Wh + H * SX;

    const int tid = threadIdx.x, wid = tid >> 5, lane = tid & 31;
    const int r = lane >> 2, q = lane & 3;
    const bool isProd = wid < PW;

    for (int idx = tid; idx < KT * H; idx += 256) {
        int k = idx / H, c = idx - k * H;
        float w = (k < CIN) ? Wa[k * H + c] : ((k == CIN) ? ba[c] : 0.f);
        __nv_bfloat16 hb = __float2bfloat16(w);
        __nv_bfloat16 lb = __float2bfloat16(w - __bfloat162float(hb));
        Wh[c * SX + k] = hb;
        Wl[c * SX + k] = lb;
    }

    auto produce = [&](int t, char* Xbuf) {
        const int base = wid * 32;
#pragma unroll
        for (int p = 0; p < 16; ++p) {
            int row = base + 2 * p + (lane >> 4);
            int c4  = lane & 15;
            int n   = t * 128 + row;
            float4 a = make_float4(0.f, 0.f, 0.f, 0.f);
            if (n < N) a = ((const float4*)(hin + (size_t)n * HC))[c4];
            *(uint2*)(Xbuf + row * RS + c4 * 8) =
                make_uint2(pack_bf16(a.x, a.y), pack_bf16(a.z, a.w));
        }
#pragma unroll
        for (int p = 0; p < (KT - HC) / 4; ++p) {
            int row = base + lane;
            int n   = t * 128 + row;
            float4 v = make_float4(0.f, 0.f, 0.f, 0.f);
            if (p == 0) {
                int nn = (n < N) ? n : (N - 1);
                v.x = pos[nn * 3]; v.y = pos[nn * 3 + 1]; v.z = pos[nn * 3 + 2];
                v.w = 1.f;
            }
            *(uint2*)(Xbuf + row * RS + (HC / 4 + p) * 8) =
                make_uint2(pack_bf16(v.x, v.y), pack_bf16(v.z, v.w));
        }
    };

    auto consume = [&](int t, const char* Xbuf) {
        const int cw = wid - PW;
        const uint32_t Xu  = smem_u32(Xbuf);
        const uint32_t WhU = smem_u32(Wh), WlU = smem_u32(Wl);
        const int arow  = (lane & 7) + 8 * ((lane >> 3) & 1);
        const int ahalf = (lane >> 4) * 16;
        const int bsel  = lane >> 3;
        const uint32_t bbase = ((bsel < 2) ? WhU : WlU) +
                               (uint32_t)((lane & 7) * SX * 2) + (bsel & 1) * 16;

        uint32_t ah[2][KC][4];
#pragma unroll
        for (int mt = 0; mt < 2; ++mt) {
            uint32_t abase = Xu +
                (uint32_t)((16 * (cw * 2 + mt) + arow) * RS) + ahalf;
#pragma unroll
            for (int kc = 0; kc < KC; ++kc)
                ldsm_x4(ah[mt][kc], abase + 32 * kc);
        }

        uint32_t bf[2][4];
        ldsm_x4(bf[0], bbase);  // nb=0, kc=0
#pragma unroll
        for (int nb = 0; nb < NB; ++nb) {
            float acc[2][2][4];
#pragma unroll
            for (int mt = 0; mt < 2; ++mt)
#pragma unroll
                for (int ch = 0; ch < 2; ++ch)
#pragma unroll
                    for (int i = 0; i < 4; ++i) acc[mt][ch][i] = 0.f;
#pragma unroll
            for (int kc = 0; kc < KC; ++kc) {
                const int cur = (nb * KC + kc) & 1;
                {
                    int nnb = nb, nkc = kc + 1;
                    if (nkc == KC) { nkc = 0; nnb = (nb + 1 < NB) ? nb + 1 : nb; }
                    ldsm_x4(bf[cur ^ 1],
                            bbase + (uint32_t)(8 * nnb * SX * 2 + 32 * nkc));
                }
                const uint32_t* b = bf[cur];
#pragma unroll
                for (int mt = 0; mt < 2; ++mt) {
                    mma16816(acc[mt][0], ah[mt][kc], b[0], b[1]);
                    mma16816(acc[mt][1], ah[mt][kc], b[2], b[3]);
                }
            }
#pragma unroll
            for (int mt = 0; mt < 2; ++mt) {
                int nbase = t * 128 + 16 * (cw * 2 + mt);
                float2 v0 = make_float2(acc[mt][0][0] + acc[mt][1][0],
                                        acc[mt][0][1] + acc[mt][1][1]);
                float2 v1 = make_float2(acc[mt][0][2] + acc[mt][1][2],
                                        acc[mt][0][3] + acc[mt][1][3]);
                int col = 8 * nb + 2 * q;
                int nA = nbase + r, nBr = nbase + r + 8;
                if (nA < N)  *(float2*)(A + (size_t)nA * H + col) = v0;
                if (nBr < N) *(float2*)(A + (size_t)nBr * H + col) = v1;
            }
        }
    };

    __syncthreads();
    const int t0 = blockIdx.x;
    if (isProd) produce(t0, Xb[0]);
    __syncthreads();

    for (int k = 0;; ++k) {
        int tc = t0 + k * gridDim.x;
        if (tc >= tiles) break;
        if (isProd) {
            int tp = tc + gridDim.x;
            if (tp < tiles) produce(tp, Xb[(k + 1) & 1]);
        } else {
            consume(tc, Xb[k & 1]);
        }
        __syncthreads();
    }
}

// ---------------------------------------------------------------------------
// Warp-specialized edge kernel, 2-term split, ldmatrix fragments.
// TPB=256: 8 nodes/128 edges; TPB=512: 16 nodes/256 edges (layer 3).
// ---------------------------------------------------------------------------
template <int H, int COUT, int TPB, int MAXB>
__global__ __launch_bounds__(TPB, MAXB)
void edge_ws_kernel(const float* __restrict__ A, const float* __restrict__ pos,
                    const int* __restrict__ src, const float* __restrict__ Wap,
                    const float* __restrict__ Wb, const float* __restrict__ bb,
                    float* __restrict__ hout, int N, int E, int tiles) {
    constexpr int WARPS = TPB / 32;
    constexpr int PW    = WARPS / 2;
    constexpr int NPN   = 2;
    constexpr int NODES = PW * NPN;
    constexpr int ROWS  = NODES * 16;
    constexpr int KC    = H / 16;
    constexpr int NB    = COUT / 8;
    constexpr int RS    = H * 2 + 16;
    constexpr int SX    = H + 8;

    extern __shared__ char smem[];
    char* Xb[2] = {smem, smem + ROWS * RS};
    __nv_bfloat16* Wh = (__nv_bfloat16*)(smem + 2 * ROWS * RS);
    __nv_bfloat16* Wl = Wh + COUT * SX;

    const int tid = threadIdx.x, wid = tid >> 5, lane = tid & 31;
    const bool isProd = wid < PW;

    for (int idx = tid; idx < H * COUT; idx += TPB) {
        int k = idx / COUT, n = idx - k * COUT;
        float w = Wb[idx];
        __nv_bfloat16 hb = __float2bfloat16(w);
        __nv_bfloat16 lb = __float2bfloat16(w - __bfloat162float(hb));
        Wh[n * SX + k] = hb;
        Wl[n * SX + k] = lb;
    }

    auto produce = [&](int t, char* Xbuf) {
        const int e0 = t * ROWS, n0t = t * NODES;
        const int pw = wid;
#pragma unroll
        for (int nn = 0; nn < NPN; ++nn) {
            const int g  = pw * NPN + nn;
            const int nd = min(n0t + g, N - 1);
            int e = e0 + 16 * g + (lane & 15);
            int srcv = (e < E) ? src[e] : 0;
            const int c4 = (H == 64) ? (lane & 15) : lane;
            float p0 = pos[nd * 3], p1 = pos[nd * 3 + 1], p2 = pos[nd * 3 + 2];
            float4 P;
            P.x = p0 * __ldg(&Wap[4 * c4 + 0]) + p1 * __ldg(&Wap[H + 4 * c4 + 0]) +
                  p2 * __ldg(&Wap[2 * H + 4 * c4 + 0]);
            P.y = p0 * __ldg(&Wap[4 * c4 + 1]) + p1 * __ldg(&Wap[H + 4 * c4 + 1]) +
                  p2 * __ldg(&Wap[2 * H + 4 * c4 + 1]);
            P.z = p0 * __ldg(&Wap[4 * c4 + 2]) + p1 * __ldg(&Wap[H + 4 * c4 + 2]) +
                  p2 * __ldg(&Wap[2 * H + 4 * c4 + 2]);
            P.w = p0 * __ldg(&Wap[4 * c4 + 3]) + p1 * __ldg(&Wap[H + 4 * c4 + 3]) +
                  p2 * __ldg(&Wap[2 * H + 4 * c4 + 3]);
            constexpr int PASSES = (H == 64) ? 8 : 16;
#pragma unroll
            for (int p = 0; p < PASSES; ++p) {
                int rowin = (H == 64) ? (2 * p + (lane >> 4)) : p;
                int j = __shfl_sync(0xffffffffu, srcv, rowin);
                const float4 a = ((const float4*)(A + (size_t)j * H))[c4];
                uint32_t h01 = cvt_hi(a.x, a.y, P.x, P.y);
                uint32_t h23 = cvt_hi(a.z, a.w, P.z, P.w);
                int row = 16 * g + rowin;
                *(uint2*)(Xbuf + row * RS + c4 * 8) = make_uint2(h01, h23);
            }
        }
    };

    auto consume = [&](int t, const char* Xbuf) {
        const int n0t = t * NODES;
        const int cw  = wid - PW;
        const uint32_t Xu  = smem_u32(Xbuf);
        const uint32_t WhU = smem_u32(Wh), WlU = smem_u32(Wl);
        const int arow  = (lane & 7) + 8 * ((lane >> 3) & 1);
        const int ahalf = (lane >> 4) * 16;
        const int bsel  = lane >> 3;
        const uint32_t bbase = ((bsel < 2) ? WhU : WlU) +
                               (uint32_t)((lane & 7) * SX * 2) + (bsel & 1) * 16;

        uint32_t ah[NPN][KC][4];
#pragma unroll
        for (int nn = 0; nn < NPN; ++nn) {
            uint32_t abase = Xu +
                (uint32_t)((16 * (cw * NPN + nn) + arow) * RS) + ahalf;
#pragma unroll
            for (int kc = 0; kc < KC; ++kc)
                ldsm_x4(ah[nn][kc], abase + 32 * kc);
        }

        uint32_t bf[2][4];
        ldsm_x4(bf[0], bbase);
#pragma unroll
        for (int nb = 0; nb < NB; ++nb) {
            float acc[NPN][2][4];
#pragma unroll
            for (int nn = 0; nn < NPN; ++nn)
#pragma unroll
                for (int ch = 0; ch < 2; ++ch)
#pragma unroll
                    for (int i = 0; i < 4; ++i) acc[nn][ch][i] = 0.f;
#pragma unroll
            for (int kc = 0; kc < KC; ++kc) {
                const int cur = (nb * KC + kc) & 1;
                {
                    int nnb = nb, nkc = kc + 1;
                    if (nkc == KC) { nkc = 0; nnb = (nb + 1 < NB) ? nb + 1 : nb; }
                    ldsm_x4(bf[cur ^ 1],
                            bbase + (uint32_t)(8 * nnb * SX * 2 + 32 * nkc));
                }
                const uint32_t* b = bf[cur];
#pragma unroll
                for (int nn = 0; nn < NPN; ++nn) {
                    mma16816(acc[nn][0], ah[nn][kc], b[0], b[1]);
                    mma16816(acc[nn][1], ah[nn][kc], b[2], b[3]);
                }
            }
#pragma unroll
            for (int nn = 0; nn < NPN; ++nn) {
                float s0 = acc[nn][0][0] + acc[nn][1][0];
                float s1 = acc[nn][0][1] + acc[nn][1][1];
                float s2 = acc[nn][0][2] + acc[nn][1][2];
                float s3 = acc[nn][0][3] + acc[nn][1][3];
                float m0 = fmaxf(s0, s2);
                float m1 = fmaxf(s1, s3);
                m0 = fmaxf(m0, __shfl_xor_sync(0xffffffffu, m0, 4));
                m1 = fmaxf(m1, __shfl_xor_sync(0xffffffffu, m1, 4));
                m0 = fmaxf(m0, __shfl_xor_sync(0xffffffffu, m0, 8));
                m1 = fmaxf(m1, __shfl_xor_sync(0xffffffffu, m1, 8));
                m0 = fmaxf(m0, __shfl_xor_sync(0xffffffffu, m0, 16));
                m1 = fmaxf(m1, __shfl_xor_sync(0xffffffffu, m1, 16));
                int node = n0t + cw * NPN + nn;
                if (lane < 4 && node < N) {
                    int col = 8 * nb + 2 * lane;
                    float2 o;
                    o.x = fmaxf(m0 + __ldg(&bb[col]), 0.f);
                    o.y = fmaxf(m1 + __ldg(&bb[col + 1]), 0.f);
                    *(float2*)(hout + (size_t)node * COUT + col) = o;
                }
            }
        }
    };

    __syncthreads();
    const int t0 = blockIdx.x;
    if (isProd) produce(t0, Xb[0]);
    __syncthreads();

    for (int k = 0;; ++k) {
        int tc = t0 + k * gridDim.x;
        if (tc >= tiles) break;
        if (isProd) {
            int tp = tc + gridDim.x;
            if (tp < tiles) produce(tp, Xb[(k + 1) & 1]);
        } else {
            consume(tc, Xb[k & 1]);
        }
        __syncthreads();
    }
}

// ---------------------------------------------------------------------------
// Deterministic two-stage mean pool (batch sorted) + regressor.
// ---------------------------------------------------------------------------
__device__ __forceinline__ int lb(const int* __restrict__ b, int n, int v) {
    int lo = 0, hi = n;
    while (lo < hi) {
        int m = (lo + hi) >> 1;
        if (b[m] < v) lo = m + 1; else hi = m;
    }
    return lo;
}

__global__ void pool1_kernel(const float* __restrict__ h3,
                             const int* __restrict__ batch, int N,
                             float* __restrict__ part) {
    int b = blockIdx.x, k = blockIdx.y, c = threadIdx.x;
    int s = lb(batch, N, b), e = lb(batch, N, b + 1);
    int len = e - s;
    int cs = s + (int)(((long long)len * k) >> 3);
    int ce = s + (int)(((long long)len * (k + 1)) >> 3);
    float s0 = 0.f, s1 = 0.f, s2 = 0.f, s3 = 0.f;
    int n = cs;
    for (; n + 3 < ce; n += 4) {
        s0 += h3[(n + 0) * 128 + c];
        s1 += h3[(n + 1) * 128 + c];
        s2 += h3[(n + 2) * 128 + c];
        s3 += h3[(n + 3) * 128 + c];
    }
    for (; n < ce; ++n) s0 += h3[n * 128 + c];
    part[(b * 8 + k) * 128 + c] = ((s0 + s1) + (s2 + s3));
}

__global__ void pool2_kernel(const float* __restrict__ part,
                             const int* __restrict__ batch, int N,
                             float* __restrict__ pool) {
    int b = blockIdx.x, c = threadIdx.x;
    int s = lb(batch, N, b), e = lb(batch, N, b + 1);
    float sum = 0.f;
#pragma unroll
    for (int k = 0; k < 8; ++k) sum += part[(b * 8 + k) * 128 + c];
    pool[b * 128 + c] = sum / fmaxf((float)(e - s), 1.f);
}

__global__ void reg_kernel(const float* __restrict__ pool,
                           const float* __restrict__ wr1, const float* __restrict__ br1,
                           const float* __restrict__ wr2, const float* __restrict__ br2,
                           float* __restrict__ out, int B) {
    int b = blockIdx.x * blockDim.x + threadIdx.x;
    if (b >= B) return;
    float o = br2[0];
    for (int j = 0; j < 64; ++j) {
        float s = br1[j];
        for (int k = 0; k < 128; ++k) s += pool[b * 128 + k] * wr1[k * 64 + j];
        o += s * wr2[j];
    }
    out[b] = 1.f / (1.f + expf(-o));
}

extern "C" void kernel_launch(void* const* d_in, const int* in_sizes, int n_in,
                              void* d_out, int out_size) {
    const float* pos   = (const float*)d_in[0];
    const int*   ei    = (const int*)d_in[1];
    const int*   batch = (const int*)d_in[2];
    const float* w1a = (const float*)d_in[4],  *b1a = (const float*)d_in[5];
    const float* w1b = (const float*)d_in[6],  *b1b = (const float*)d_in[7];
    const float* w2a = (const float*)d_in[8],  *b2a = (const float*)d_in[9];
    const float* w2b = (const float*)d_in[10], *b2b = (const float*)d_in[11];
    const float* w3a = (const float*)d_in[12], *b3a = (const float*)d_in[13];
    const float* w3b = (const float*)d_in[14], *b3b = (const float*)d_in[15];
    const float* wr1 = (const float*)d_in[16], *br1 = (const float*)d_in[17];
    const float* wr2 = (const float*)d_in[18], *br2 = (const float*)d_in[19];
    float* out = (float*)d_out;

    int N = in_sizes[0] / 3;
    int E = in_sizes[1] / 2;
    int B = out_size;
    const int* srcp = ei;

    float *Abuf, *h1, *h2, *h3, *part, *pl;
    cudaGetSymbolAddress((void**)&Abuf, g_A);
    cudaGetSymbolAddress((void**)&h1, g_h1);
    cudaGetSymbolAddress((void**)&h2, g_h2);
    cudaGetSymbolAddress((void**)&h3, g_h3);
    cudaGetSymbolAddress((void**)&part, g_part);
    cudaGetSymbolAddress((void**)&pl, g_pool);

    const int smemN1 = (128 * 8 + 8 * 64) * 4;
    const int smemNM2 = 2 * 128 * 176 + 2 * 64 * 88 * 2;    //  67584
    const int smemNM3 = 2 * 128 * 176 + 2 * 128 * 88 * 2;   //  90112
    const int smemE12 = 2 * 128 * (64 * 2 + 16) + 2 * 64 * 72 * 2;    //  55296
    const int smemE3  = 2 * 256 * (128 * 2 + 16) + 2 * 128 * 136 * 2; // 208896

    cudaFuncSetAttribute(node_kernel<3, 64>,
                         cudaFuncAttributeMaxDynamicSharedMemorySize, smemN1);
    cudaFuncSetAttribute(node_mma_kernel<64, 64, 3>,
                         cudaFuncAttributeMaxDynamicSharedMemorySize, smemNM2);
    cudaFuncSetAttribute(node_mma_kernel<64, 128, 2>,
                         cudaFuncAttributeMaxDynamicSharedMemorySize, smemNM3);
    cudaFuncSetAttribute(edge_ws_kernel<64, 64, 256, 3>,
                         cudaFuncAttributeMaxDynamicSharedMemorySize, smemE12);
    cudaFuncSetAttribute(edge_ws_kernel<128, 128, 512, 1>,
                         cudaFuncAttributeMaxDynamicSharedMemorySize, smemE3);

    int tilesN = (N + 127) / 128;
    int tilesE12 = (E + 127) / 128;
    int tilesE3  = (E + 255) / 256;
    int gridN2 = tilesN < 444 ? tilesN : 444;
    int gridN3 = tilesN < 296 ? tilesN : 296;
    int grid12 = tilesE12 < 444 ? tilesE12 : 444;
    int grid3  = tilesE3 < 148 ? tilesE3 : 148;

    // layer 1 (h = pos)
    node_kernel<3, 64><<<tilesN, 256, smemN1>>>(pos, pos, w1a, b1a, Abuf, N);
    edge_ws_kernel<64, 64, 256, 3><<<grid12, 256, smemE12>>>(
        Abuf, pos, srcp, w1a + 3 * 64, w1b, b1b, h1, N, E, tilesE12);
    // layer 2
    node_mma_kernel<64, 64, 3><<<gridN2, 256, smemNM2>>>(
        h1, pos, w2a, b2a, Abuf, N, tilesN);
    edge_ws_kernel<64, 64, 256, 3><<<grid12, 256, smemE12>>>(
        Abuf, pos, srcp, w2a + 64 * 64, w2b, b2b, h2, N, E, tilesE12);
    // layer 3
    node_mma_kernel<64, 128, 2><<<gridN3, 256, smemNM3>>>(
        h2, pos, w3a, b3a, Abuf, N, tilesN);
    edge_ws_kernel<128, 128, 512, 1><<<grid3, 512, smemE3>>>(
        Abuf, pos, srcp, w3a + 64 * 128, w3b, b3b, h3, N, E, tilesE3);
    // pool + regressor
    pool1_kernel<<<dim3(B, 8), 128>>>(h3, batch, N, part);
    pool2_kernel<<<B, 128>>>(part, batch, N, pl);
    reg_kernel<<<1, 64>>>(pl, wr1, br1, wr2, br2, out, B);
}